// round 2
// baseline (speedup 1.0000x reference)
#include <cuda_runtime.h>
#include <cuda_bf16.h>
#include <cstdint>
#include <math.h>

#define BB 8192
#define HH 4096
#define GHH 1024

// ---------------- scratch (device globals; allocation-free rule) ----------------
__device__ __nv_bfloat16 g_hidden_bf[(size_t)BB * HH];
__device__ __nv_bfloat16 g_Wsim_bf[(size_t)HH * HH];
__device__ __nv_bfloat16 g_Wval_bf[(size_t)HH * HH];
__device__ __nv_bfloat16 g_Wg1_bf[(size_t)GHH * 2 * HH];
__device__ __nv_bfloat16 g_Wg2_bf[(size_t)HH * GHH];
__device__ __nv_bfloat16 g_proj_bf[(size_t)BB * HH];      // proj -> normed (in place)
__device__ __nv_bfloat16 g_values_bf[(size_t)BB * HH];
__device__ __nv_bfloat16 g_valuesT_bf[(size_t)HH * BB];
__device__ float         g_sim_f32[(size_t)BB * BB];
__device__ __nv_bfloat16 g_weights_bf[(size_t)BB * BB];
__device__ __nv_bfloat16 g_cross_bf[(size_t)BB * HH];
__device__ __nv_bfloat16 g_gatein_bf[(size_t)BB * 2 * HH];
__device__ __nv_bfloat16 g_h1_bf[(size_t)BB * GHH];
__device__ unsigned char g_mask_u8[BB];
__device__ int           g_mask_code;

// ---------------- helpers ----------------
__device__ __forceinline__ uint32_t smem_u32(const void* p) {
    return (uint32_t)__cvta_generic_to_shared(p);
}

// ---------------- mask dtype sniffing (bool could arrive as u8/i32/f32/bf16) ----
__global__ void detect_mask_kernel(const unsigned char* m) {
    __shared__ int s_nonbin, s_off4, s_fbad, s_bfbad;
    if (threadIdx.x == 0) { s_nonbin = 0; s_off4 = 0; s_fbad = 0; s_bfbad = 0; }
    __syncthreads();
    int nonbin = 0, off4 = 0, fbad = 0, bfbad = 0;
    for (int j = threadIdx.x; j < 8192; j += 256) {
        unsigned char b = m[j];
        if (b > 1) nonbin++;
        if ((j & 3) != 0 && b != 0) off4++;
    }
    const uint32_t* u = (const uint32_t*)m;
    for (int i = threadIdx.x; i < 2048; i += 256) {
        uint32_t w = u[i];
        if (!(w == 0u || w == 0x3f800000u)) fbad++;
    }
    const uint16_t* h = (const uint16_t*)m;
    for (int i = threadIdx.x; i < 4096; i += 256) {
        uint16_t x = h[i];
        if (!(x == 0 || x == 0x3f80)) bfbad++;
    }
    atomicAdd(&s_nonbin, nonbin);
    atomicAdd(&s_off4, off4);
    atomicAdd(&s_fbad, fbad);
    atomicAdd(&s_bfbad, bfbad);
    __syncthreads();
    if (threadIdx.x == 0) {
        int code;
        if (s_nonbin == 0) code = (s_off4 > 0) ? 0 : 1;   // 0=u8, 1=i32
        else if (s_fbad == 0) code = 2;                   // f32
        else if (s_bfbad == 0) code = 3;                  // bf16
        else code = 1;
        g_mask_code = code;
    }
}

__global__ void expand_mask_kernel(const void* m, unsigned char* out) {
    int i = blockIdx.x * blockDim.x + threadIdx.x;
    if (i >= BB) return;
    int code = g_mask_code;
    bool v;
    if (code == 0)      v = ((const unsigned char*)m)[i] != 0;
    else if (code == 1) v = ((const int*)m)[i] != 0;
    else if (code == 2) v = ((const float*)m)[i] != 0.0f;
    else                v = (((const uint16_t*)m)[i] & 0x7fff) != 0;
    out[i] = v ? 1 : 0;
}

// ---------------- fp32 -> bf16 convert ----------------
__global__ void f32_to_bf16_kernel(const float* __restrict__ in,
                                   __nv_bfloat16* __restrict__ out, long n2) {
    long i = (long)blockIdx.x * blockDim.x + threadIdx.x;
    if (i < n2) {
        float2 v = ((const float2*)in)[i];
        ((__nv_bfloat162*)out)[i] = __floats2bfloat162_rn(v.x, v.y);
    }
}

// ---------------- row L2 normalize (in place, bf16) ----------------
__global__ void normalize_rows_kernel(__nv_bfloat16* p) {
    int row = blockIdx.x;
    __nv_bfloat16* r = p + (size_t)row * HH;
    float s = 0.f;
    for (int j = threadIdx.x; j < HH; j += 256) {
        float v = __bfloat162float(r[j]);
        s += v * v;
    }
#pragma unroll
    for (int o = 16; o > 0; o >>= 1) s += __shfl_xor_sync(0xffffffffu, s, o);
    __shared__ float ws[8];
    int w = threadIdx.x >> 5, l = threadIdx.x & 31;
    if (l == 0) ws[w] = s;
    __syncthreads();
    if (threadIdx.x < 32) {
        float x = (threadIdx.x < 8) ? ws[threadIdx.x] : 0.f;
#pragma unroll
        for (int o = 4; o > 0; o >>= 1) x += __shfl_xor_sync(0xffffffffu, x, o);
        if (threadIdx.x == 0) ws[0] = x;
    }
    __syncthreads();
    float tot = ws[0];
    float scale = 1.f / fmaxf(sqrtf(tot), 1e-12f);
    for (int j = threadIdx.x; j < HH; j += 256) {
        float v = __bfloat162float(r[j]);
        r[j] = __float2bfloat16(v * scale);
    }
}

// ---------------- masked softmax over sim rows -> bf16 weights ----------------
__global__ void softmax_mask_kernel(const float* __restrict__ sim,
                                    const unsigned char* __restrict__ mask,
                                    __nv_bfloat16* __restrict__ wts) {
    int row = blockIdx.x;
    __shared__ float sv[BB];
    __shared__ float red[8];
    const float* sr = sim + (size_t)row * BB;
    float mx = -INFINITY;
    for (int j = threadIdx.x; j < BB; j += 256) {
        float v = sr[j];
        if (j == row || mask[j] == 0) v = -INFINITY;
        sv[j] = v;
        mx = fmaxf(mx, v);
    }
#pragma unroll
    for (int o = 16; o > 0; o >>= 1) mx = fmaxf(mx, __shfl_xor_sync(0xffffffffu, mx, o));
    int w = threadIdx.x >> 5, l = threadIdx.x & 31;
    if (l == 0) red[w] = mx;
    __syncthreads();
    if (threadIdx.x < 32) {
        float x = (threadIdx.x < 8) ? red[threadIdx.x] : -INFINITY;
#pragma unroll
        for (int o = 4; o > 0; o >>= 1) x = fmaxf(x, __shfl_xor_sync(0xffffffffu, x, o));
        if (threadIdx.x == 0) red[0] = x;
    }
    __syncthreads();
    float M = red[0];
    __syncthreads();
    float sum = 0.f;
    for (int j = threadIdx.x; j < BB; j += 256) {
        float v = sv[j];
        float e = (v == -INFINITY) ? 0.f : __expf(v - M);
        sv[j] = e;
        sum += e;
    }
#pragma unroll
    for (int o = 16; o > 0; o >>= 1) sum += __shfl_xor_sync(0xffffffffu, sum, o);
    if (l == 0) red[w] = sum;
    __syncthreads();
    if (threadIdx.x < 32) {
        float x = (threadIdx.x < 8) ? red[threadIdx.x] : 0.f;
#pragma unroll
        for (int o = 4; o > 0; o >>= 1) x += __shfl_xor_sync(0xffffffffu, x, o);
        if (threadIdx.x == 0) red[0] = x;
    }
    __syncthreads();
    float S = red[0];
    float inv = (S > 0.f) ? 1.f / S : 0.f;   // nan_to_num semantics
    __nv_bfloat16* wr = wts + (size_t)row * BB;
    for (int j = threadIdx.x; j < BB; j += 256)
        wr[j] = __float2bfloat16(sv[j] * inv);
}

// ---------------- bf16 transpose (values -> valuesT) ----------------
__global__ void transpose_bf16_kernel(const __nv_bfloat16* __restrict__ in,
                                      __nv_bfloat16* __restrict__ out, int R, int C) {
    __shared__ __nv_bfloat16 tile[32][33];
    int x = blockIdx.x * 32 + threadIdx.x;   // column in 'in' (C dim)
    int y0 = blockIdx.y * 32 + threadIdx.y;  // row in 'in' (R dim)
#pragma unroll
    for (int i = 0; i < 32; i += 8)
        tile[threadIdx.y + i][threadIdx.x] = in[(size_t)(y0 + i) * C + x];
    __syncthreads();
    int x2 = blockIdx.y * 32 + threadIdx.x;  // column in 'out' (R dim)
    int y2 = blockIdx.x * 32 + threadIdx.y;  // row in 'out' (C dim)
#pragma unroll
    for (int i = 0; i < 32; i += 8)
        out[(size_t)(y2 + i) * R + x2] = tile[threadIdx.x][threadIdx.y + i];
}

// ---------------- concat [hidden, cross] -> gate_in ----------------
__global__ void concat_kernel(const __nv_bfloat16* __restrict__ h,
                              const __nv_bfloat16* __restrict__ c,
                              __nv_bfloat16* __restrict__ gi) {
    long i4 = ((long)blockIdx.x * blockDim.x + threadIdx.x) * 4;
    if (i4 >= (long)BB * 2 * HH) return;
    long b = i4 >> 13;           // 2H = 8192
    int j = (int)(i4 & 8191);
    const __nv_bfloat16* src = (j < HH) ? (h + b * HH + j) : (c + b * HH + (j - HH));
    *(uint64_t*)(gi + i4) = *(const uint64_t*)src;
}

// ---------------- bf16 NT GEMM: C[M,N] = A[M,K] * B[N,K]^T ----------------
// 128x128x32 tile, 256 threads (8 warps, 2x4 -> 64x32 warp tile),
// cp.async double buffered smem, ldmatrix fragments, m16n8k16 bf16 mma.
// EPI: 0 = f32 store, 1 = bf16 store, 2 = gelu(x+bias) -> bf16,
//      3 = out = hid + sigmoid(x+bias)*cross -> f32.
template <int EPI>
__global__ void __launch_bounds__(256, 1)
gemm_nt_kernel(const __nv_bfloat16* __restrict__ A,
               const __nv_bfloat16* __restrict__ Bm,
               void* __restrict__ Cv,
               int M, int N, int K,
               const float* __restrict__ bias,
               const float* __restrict__ hid,
               const __nv_bfloat16* __restrict__ crossp) {
    __shared__ __align__(16) __nv_bfloat16 sA[2][128 * 40];  // 80B row stride (pad 8 halves)
    __shared__ __align__(16) __nv_bfloat16 sB[2][128 * 40];

    const int t = threadIdx.x;
    const int warp = t >> 5, lane = t & 31;
    const int wm = (warp & 1) * 64;
    const int wn = (warp >> 1) * 32;
    const int m0 = blockIdx.y * 128;
    const int n0 = blockIdx.x * 128;
    const int KT = K >> 5;

    float acc[4][4][4];
#pragma unroll
    for (int i = 0; i < 4; i++)
#pragma unroll
        for (int j = 0; j < 4; j++)
#pragma unroll
            for (int r = 0; r < 4; r++) acc[i][j][r] = 0.f;

    auto load_stage = [&](int kt, int st) {
        const __nv_bfloat16* Ag = A + (size_t)m0 * K + (size_t)kt * 32;
        const __nv_bfloat16* Bg = Bm + (size_t)n0 * K + (size_t)kt * 32;
        uint32_t sa = smem_u32(&sA[st][0]);
        uint32_t sb = smem_u32(&sB[st][0]);
#pragma unroll
        for (int i = 0; i < 2; i++) {
            int idx = t + i * 256;       // 0..511
            int row = idx >> 2, ch = idx & 3;
            uint32_t da = sa + row * 80 + ch * 16;
            const void* pa = Ag + (size_t)row * K + ch * 8;
            asm volatile("cp.async.cg.shared.global [%0], [%1], 16;\n" ::"r"(da), "l"(pa));
            uint32_t db = sb + row * 80 + ch * 16;
            const void* pb = Bg + (size_t)row * K + ch * 8;
            asm volatile("cp.async.cg.shared.global [%0], [%1], 16;\n" ::"r"(db), "l"(pb));
        }
    };

    load_stage(0, 0);
    asm volatile("cp.async.commit_group;\n" ::);

    for (int kt = 0; kt < KT; ++kt) {
        int st = kt & 1;
        if (kt + 1 < KT) load_stage(kt + 1, st ^ 1);
        asm volatile("cp.async.commit_group;\n" ::);
        asm volatile("cp.async.wait_group 1;\n" ::);
        __syncthreads();

        uint32_t aB = smem_u32(&sA[st][0]);
        uint32_t bB = smem_u32(&sB[st][0]);
#pragma unroll
        for (int ks = 0; ks < 2; ++ks) {
            uint32_t af[4][4], bf[2][4];
#pragma unroll
            for (int i = 0; i < 4; i++) {
                uint32_t addr = aB + (uint32_t)((wm + i * 16 + (lane & 15)) * 80 +
                                                (ks * 16 + (lane >> 4) * 8) * 2);
                asm volatile("ldmatrix.sync.aligned.m8n8.x4.shared.b16 {%0,%1,%2,%3}, [%4];\n"
                             : "=r"(af[i][0]), "=r"(af[i][1]), "=r"(af[i][2]), "=r"(af[i][3])
                             : "r"(addr));
            }
#pragma unroll
            for (int jj = 0; jj < 2; jj++) {
                uint32_t addr = bB + (uint32_t)((wn + jj * 16 + (lane & 15)) * 80 +
                                                (ks * 16 + (lane >> 4) * 8) * 2);
                asm volatile("ldmatrix.sync.aligned.m8n8.x4.shared.b16 {%0,%1,%2,%3}, [%4];\n"
                             : "=r"(bf[jj][0]), "=r"(bf[jj][1]), "=r"(bf[jj][2]), "=r"(bf[jj][3])
                             : "r"(addr));
            }
#pragma unroll
            for (int i = 0; i < 4; i++) {
#pragma unroll
                for (int j = 0; j < 4; j++) {
                    const int jj = j >> 1, s = j & 1;
                    asm volatile(
                        "mma.sync.aligned.m16n8k16.row.col.f32.bf16.bf16.f32 "
                        "{%0,%1,%2,%3}, {%4,%5,%6,%7}, {%8,%9}, {%0,%1,%2,%3};\n"
                        : "+f"(acc[i][j][0]), "+f"(acc[i][j][1]),
                          "+f"(acc[i][j][2]), "+f"(acc[i][j][3])
                        : "r"(af[i][0]), "r"(af[i][1]), "r"(af[i][2]), "r"(af[i][3]),
                          "r"(bf[jj][s]), "r"(bf[jj][s + 2]));
                }
            }
        }
        __syncthreads();
    }

    // ----- epilogue -----
#pragma unroll
    for (int i = 0; i < 4; i++) {
        int row0 = m0 + wm + i * 16 + (lane >> 2);
#pragma unroll
        for (int j = 0; j < 4; j++) {
            int col = n0 + wn + j * 8 + (lane & 3) * 2;
#pragma unroll
            for (int h = 0; h < 2; h++) {
                int r = row0 + h * 8;
                float v0 = acc[i][j][h * 2 + 0];
                float v1 = acc[i][j][h * 2 + 1];
                size_t off = (size_t)r * N + col;
                if (EPI == 0) {
                    *(float2*)((float*)Cv + off) = make_float2(v0, v1);
                } else if (EPI == 1) {
                    *(__nv_bfloat162*)((__nv_bfloat16*)Cv + off) =
                        __floats2bfloat162_rn(v0, v1);
                } else if (EPI == 2) {
                    float x0 = v0 + bias[col], x1 = v1 + bias[col + 1];
                    float g0 = 0.5f * x0 * (1.f + erff(x0 * 0.70710678118654752f));
                    float g1 = 0.5f * x1 * (1.f + erff(x1 * 0.70710678118654752f));
                    *(__nv_bfloat162*)((__nv_bfloat16*)Cv + off) =
                        __floats2bfloat162_rn(g0, g1);
                } else {
                    float x0 = v0 + bias[col], x1 = v1 + bias[col + 1];
                    float s0 = 1.f / (1.f + expf(-x0));
                    float s1 = 1.f / (1.f + expf(-x1));
                    __nv_bfloat162 cc = *(const __nv_bfloat162*)(crossp + off);
                    float2 hv = *(const float2*)(hid + off);
                    *(float2*)((float*)Cv + off) =
                        make_float2(hv.x + s0 * __bfloat162float(cc.x),
                                    hv.y + s1 * __bfloat162float(cc.y));
                }
            }
        }
    }
}

// ---------------- host launcher ----------------
extern "C" void kernel_launch(void* const* d_in, const int* in_sizes, int n_in,
                              void* d_out, int out_size) {
    (void)in_sizes; (void)n_in; (void)out_size;
    const float* hidden = (const float*)d_in[0];
    const void*  amask  = d_in[1];
    const float* Wsim   = (const float*)d_in[2];
    const float* Wval   = (const float*)d_in[3];
    const float* Wg1    = (const float*)d_in[4];
    const float* bg1    = (const float*)d_in[5];
    const float* Wg2    = (const float*)d_in[6];
    const float* bg2    = (const float*)d_in[7];
    float* out = (float*)d_out;

    __nv_bfloat16 *hbf, *wsim, *wval, *wg1, *wg2, *proj, *vals, *valsT, *wts, *cross, *gin, *h1;
    float* sim;
    unsigned char* mask;
    cudaGetSymbolAddress((void**)&hbf,   g_hidden_bf);
    cudaGetSymbolAddress((void**)&wsim,  g_Wsim_bf);
    cudaGetSymbolAddress((void**)&wval,  g_Wval_bf);
    cudaGetSymbolAddress((void**)&wg1,   g_Wg1_bf);
    cudaGetSymbolAddress((void**)&wg2,   g_Wg2_bf);
    cudaGetSymbolAddress((void**)&proj,  g_proj_bf);
    cudaGetSymbolAddress((void**)&vals,  g_values_bf);
    cudaGetSymbolAddress((void**)&valsT, g_valuesT_bf);
    cudaGetSymbolAddress((void**)&sim,   g_sim_f32);
    cudaGetSymbolAddress((void**)&wts,   g_weights_bf);
    cudaGetSymbolAddress((void**)&cross, g_cross_bf);
    cudaGetSymbolAddress((void**)&gin,   g_gatein_bf);
    cudaGetSymbolAddress((void**)&h1,    g_h1_bf);
    cudaGetSymbolAddress((void**)&mask,  g_mask_u8);

    // mask dtype sniff + canonicalize
    detect_mask_kernel<<<1, 256>>>((const unsigned char*)amask);
    expand_mask_kernel<<<(BB + 255) / 256, 256>>>(amask, mask);

    // fp32 -> bf16 conversions
    {
        long n2;
        n2 = (long)BB * HH / 2;
        f32_to_bf16_kernel<<<(unsigned)((n2 + 255) / 256), 256>>>(hidden, hbf, n2);
        n2 = (long)HH * HH / 2;
        f32_to_bf16_kernel<<<(unsigned)((n2 + 255) / 256), 256>>>(Wsim, wsim, n2);
        f32_to_bf16_kernel<<<(unsigned)((n2 + 255) / 256), 256>>>(Wval, wval, n2);
        n2 = (long)GHH * 2 * HH / 2;
        f32_to_bf16_kernel<<<(unsigned)((n2 + 255) / 256), 256>>>(Wg1, wg1, n2);
        n2 = (long)HH * GHH / 2;
        f32_to_bf16_kernel<<<(unsigned)((n2 + 255) / 256), 256>>>(Wg2, wg2, n2);
    }

    // 1) proj = hidden @ Wsim^T  (bf16 out)
    gemm_nt_kernel<1><<<dim3(HH / 128, BB / 128), 256>>>(hbf, wsim, proj, BB, HH, HH,
                                                         nullptr, nullptr, nullptr);
    // 2) L2 normalize rows (in place)
    normalize_rows_kernel<<<BB, 256>>>(proj);
    // 3) sim = normed @ normed^T (f32 out)
    gemm_nt_kernel<0><<<dim3(BB / 128, BB / 128), 256>>>(proj, proj, sim, BB, BB, HH,
                                                         nullptr, nullptr, nullptr);
    // 4) masked softmax -> weights (bf16)
    softmax_mask_kernel<<<BB, 256>>>(sim, mask, wts);
    // 5) values = hidden @ Wval^T (bf16)
    gemm_nt_kernel<1><<<dim3(HH / 128, BB / 128), 256>>>(hbf, wval, vals, BB, HH, HH,
                                                         nullptr, nullptr, nullptr);
    // 6) transpose values -> valuesT [H,B]
    transpose_bf16_kernel<<<dim3(HH / 32, BB / 32), dim3(32, 8)>>>(vals, valsT, BB, HH);
    // 7) cross = weights @ values  == weights(NT) valuesT  (bf16)
    gemm_nt_kernel<1><<<dim3(HH / 128, BB / 128), 256>>>(wts, valsT, cross, BB, HH, BB,
                                                         nullptr, nullptr, nullptr);
    // 8) gate_in = concat(hidden, cross)
    concat_kernel<<<(unsigned)(((long)BB * 2 * HH / 4 + 255) / 256), 256>>>(hbf, cross, gin);
    // 9) h1 = gelu(gate_in @ Wg1^T + b1) (bf16)
    gemm_nt_kernel<2><<<dim3(GHH / 128, BB / 128), 256>>>(gin, wg1, h1, BB, GHH, 2 * HH,
                                                          bg1, nullptr, nullptr);
    // 10) out = hidden + sigmoid(h1 @ Wg2^T + b2) * cross (f32)
    gemm_nt_kernel<3><<<dim3(HH / 128, BB / 128), 256>>>(h1, wg2, out, BB, HH, GHH,
                                                         bg2, hidden, cross);
}

// round 4
// speedup vs baseline: 1.0505x; 1.0505x over previous
#include <cuda_runtime.h>
#include <cuda_bf16.h>
#include <cstdint>
#include <math.h>

#define BB 8192
#define HH 4096
#define GHH 1024

// ---------------- scratch (device globals; allocation-free rule) ----------------
__device__ __nv_bfloat16 g_hidden_bf[(size_t)BB * HH];
__device__ __nv_bfloat16 g_Wsim_bf[(size_t)HH * HH];
__device__ __nv_bfloat16 g_Wval_bf[(size_t)HH * HH];
__device__ __nv_bfloat16 g_Wg1_bf[(size_t)GHH * 2 * HH];
__device__ __nv_bfloat16 g_Wg2_bf[(size_t)HH * GHH];
__device__ __nv_bfloat16 g_proj_bf[(size_t)BB * HH];
__device__ __nv_bfloat16 g_values_bf[(size_t)BB * HH];
__device__ __nv_bfloat16 g_valuesT_bf[(size_t)HH * BB];
__device__ float         g_sim_f32[(size_t)BB * BB];
__device__ __nv_bfloat16 g_weights_bf[(size_t)BB * BB];
__device__ __nv_bfloat16 g_cross_bf[(size_t)BB * HH];
__device__ __nv_bfloat16 g_gatein_bf[(size_t)BB * 2 * HH];
__device__ __nv_bfloat16 g_h1_bf[(size_t)BB * GHH];
__device__ unsigned char g_mask_u8[BB];
__device__ int           g_mask_code;

// ---------------- helpers ----------------
__device__ __forceinline__ uint32_t smem_u32(const void* p) {
    return (uint32_t)__cvta_generic_to_shared(p);
}

// ---------------- mask dtype sniffing ----------------
__global__ void detect_mask_kernel(const unsigned char* m) {
    __shared__ int s_nonbin, s_off4, s_fbad, s_bfbad;
    if (threadIdx.x == 0) { s_nonbin = 0; s_off4 = 0; s_fbad = 0; s_bfbad = 0; }
    __syncthreads();
    int nonbin = 0, off4 = 0, fbad = 0, bfbad = 0;
    for (int j = threadIdx.x; j < 8192; j += 256) {
        unsigned char b = m[j];
        if (b > 1) nonbin++;
        if ((j & 3) != 0 && b != 0) off4++;
    }
    const uint32_t* u = (const uint32_t*)m;
    for (int i = threadIdx.x; i < 2048; i += 256) {
        uint32_t w = u[i];
        if (!(w == 0u || w == 0x3f800000u)) fbad++;
    }
    const uint16_t* h = (const uint16_t*)m;
    for (int i = threadIdx.x; i < 4096; i += 256) {
        uint16_t x = h[i];
        if (!(x == 0 || x == 0x3f80)) bfbad++;
    }
    atomicAdd(&s_nonbin, nonbin);
    atomicAdd(&s_off4, off4);
    atomicAdd(&s_fbad, fbad);
    atomicAdd(&s_bfbad, bfbad);
    __syncthreads();
    if (threadIdx.x == 0) {
        int code;
        if (s_nonbin == 0) code = (s_off4 > 0) ? 0 : 1;
        else if (s_fbad == 0) code = 2;
        else if (s_bfbad == 0) code = 3;
        else code = 1;
        g_mask_code = code;
    }
}

__global__ void expand_mask_kernel(const void* m, unsigned char* out) {
    int i = blockIdx.x * blockDim.x + threadIdx.x;
    if (i >= BB) return;
    int code = g_mask_code;
    bool v;
    if (code == 0)      v = ((const unsigned char*)m)[i] != 0;
    else if (code == 1) v = ((const int*)m)[i] != 0;
    else if (code == 2) v = ((const float*)m)[i] != 0.0f;
    else                v = (((const uint16_t*)m)[i] & 0x7fff) != 0;
    out[i] = v ? 1 : 0;
}

// ---------------- fp32 -> bf16 ----------------
__global__ void f32_to_bf16_kernel(const float* __restrict__ in,
                                   __nv_bfloat16* __restrict__ out, long n2) {
    long i = (long)blockIdx.x * blockDim.x + threadIdx.x;
    if (i < n2) {
        float2 v = ((const float2*)in)[i];
        ((__nv_bfloat162*)out)[i] = __floats2bfloat162_rn(v.x, v.y);
    }
}

// ---------------- row L2 normalize ----------------
__global__ void normalize_rows_kernel(__nv_bfloat16* p) {
    int row = blockIdx.x;
    __nv_bfloat16* r = p + (size_t)row * HH;
    float s = 0.f;
    for (int j = threadIdx.x; j < HH; j += 256) {
        float v = __bfloat162float(r[j]);
        s += v * v;
    }
#pragma unroll
    for (int o = 16; o > 0; o >>= 1) s += __shfl_xor_sync(0xffffffffu, s, o);
    __shared__ float ws[8];
    int w = threadIdx.x >> 5, l = threadIdx.x & 31;
    if (l == 0) ws[w] = s;
    __syncthreads();
    if (threadIdx.x < 32) {
        float x = (threadIdx.x < 8) ? ws[threadIdx.x] : 0.f;
#pragma unroll
        for (int o = 4; o > 0; o >>= 1) x += __shfl_xor_sync(0xffffffffu, x, o);
        if (threadIdx.x == 0) ws[0] = x;
    }
    __syncthreads();
    float scale = 1.f / fmaxf(sqrtf(ws[0]), 1e-12f);
    for (int j = threadIdx.x; j < HH; j += 256) {
        float v = __bfloat162float(r[j]);
        r[j] = __float2bfloat16(v * scale);
    }
}

// ---------------- masked softmax ----------------
__global__ void softmax_mask_kernel(const float* __restrict__ sim,
                                    const unsigned char* __restrict__ mask,
                                    __nv_bfloat16* __restrict__ wts) {
    int row = blockIdx.x;
    __shared__ float sv[BB];
    __shared__ float red[8];
    const float* sr = sim + (size_t)row * BB;
    float mx = -INFINITY;
    for (int j = threadIdx.x; j < BB; j += 256) {
        float v = sr[j];
        if (j == row || mask[j] == 0) v = -INFINITY;
        sv[j] = v;
        mx = fmaxf(mx, v);
    }
#pragma unroll
    for (int o = 16; o > 0; o >>= 1) mx = fmaxf(mx, __shfl_xor_sync(0xffffffffu, mx, o));
    int w = threadIdx.x >> 5, l = threadIdx.x & 31;
    if (l == 0) red[w] = mx;
    __syncthreads();
    if (threadIdx.x < 32) {
        float x = (threadIdx.x < 8) ? red[threadIdx.x] : -INFINITY;
#pragma unroll
        for (int o = 4; o > 0; o >>= 1) x = fmaxf(x, __shfl_xor_sync(0xffffffffu, x, o));
        if (threadIdx.x == 0) red[0] = x;
    }
    __syncthreads();
    float M = red[0];
    __syncthreads();
    float sum = 0.f;
    for (int j = threadIdx.x; j < BB; j += 256) {
        float v = sv[j];
        float e = (v == -INFINITY) ? 0.f : __expf(v - M);
        sv[j] = e;
        sum += e;
    }
#pragma unroll
    for (int o = 16; o > 0; o >>= 1) sum += __shfl_xor_sync(0xffffffffu, sum, o);
    if (l == 0) red[w] = sum;
    __syncthreads();
    if (threadIdx.x < 32) {
        float x = (threadIdx.x < 8) ? red[threadIdx.x] : 0.f;
#pragma unroll
        for (int o = 4; o > 0; o >>= 1) x += __shfl_xor_sync(0xffffffffu, x, o);
        if (threadIdx.x == 0) red[0] = x;
    }
    __syncthreads();
    float S = red[0];
    float inv = (S > 0.f) ? 1.f / S : 0.f;
    __nv_bfloat16* wr = wts + (size_t)row * BB;
    for (int j = threadIdx.x; j < BB; j += 256)
        wr[j] = __float2bfloat16(sv[j] * inv);
}

// ---------------- bf16 transpose ----------------
__global__ void transpose_bf16_kernel(const __nv_bfloat16* __restrict__ in,
                                      __nv_bfloat16* __restrict__ out, int R, int C) {
    __shared__ __nv_bfloat16 tile[32][33];
    int x = blockIdx.x * 32 + threadIdx.x;
    int y0 = blockIdx.y * 32 + threadIdx.y;
#pragma unroll
    for (int i = 0; i < 32; i += 8)
        tile[threadIdx.y + i][threadIdx.x] = in[(size_t)(y0 + i) * C + x];
    __syncthreads();
    int x2 = blockIdx.y * 32 + threadIdx.x;
    int y2 = blockIdx.x * 32 + threadIdx.y;
#pragma unroll
    for (int i = 0; i < 32; i += 8)
        out[(size_t)(y2 + i) * R + x2] = tile[threadIdx.x][threadIdx.y + i];
}

// ---------------- concat ----------------
__global__ void concat_kernel(const __nv_bfloat16* __restrict__ h,
                              const __nv_bfloat16* __restrict__ c,
                              __nv_bfloat16* __restrict__ gi) {
    long i4 = ((long)blockIdx.x * blockDim.x + threadIdx.x) * 4;
    if (i4 >= (long)BB * 2 * HH) return;
    long b = i4 >> 13;
    int j = (int)(i4 & 8191);
    const __nv_bfloat16* src = (j < HH) ? (h + b * HH + j) : (c + b * HH + (j - HH));
    *(uint64_t*)(gi + i4) = *(const uint64_t*)src;
}

// ================= bf16 NT GEMM (mma.sync): C[M,N] = A[M,K] * B[N,K]^T ========
// CTA tile 128x256, warp tile 64x64 (8 warps, 2M x 4N), K-stage 64,
// 3-stage cp.async pipeline. smem row stride 144B (conflict-free ldmatrix).
// EPI: 0=f32, 1=bf16, 2=gelu(x+bias)->bf16, 3=hid+sigmoid(x+bias)*cross->f32
#define SROWB 144                      // bytes per 64-element bf16 row (128 data + 16 pad)
#define A_BYTES (128 * SROWB)          // 18432
#define B_BYTES (256 * SROWB)          // 36864
#define STAGE_BYTES (A_BYTES + B_BYTES)  // 55296
#define GEMM_DYN_SMEM (3 * STAGE_BYTES + 256)

template <int EPI>
__global__ void __launch_bounds__(256, 1)
gemm_nt_kernel(const __nv_bfloat16* __restrict__ A,
               const __nv_bfloat16* __restrict__ Bm,
               void* __restrict__ Cv,
               int M, int N, int K,
               const float* __restrict__ bias,
               const float* __restrict__ hid,
               const __nv_bfloat16* __restrict__ crossp) {
    extern __shared__ char dynsm[];
    const uint32_t sbase = (smem_u32(dynsm) + 127u) & ~127u;

    const int t = threadIdx.x;
    const int warp = t >> 5, lane = t & 31;
    const int wm = (warp & 1) * 64;        // M offset of warp tile
    const int wn = (warp >> 1) * 64;       // N offset of warp tile
    const int m0 = blockIdx.y * 128;
    const int n0 = blockIdx.x * 256;
    const int KT = K >> 6;                 // 64-wide K stages

    float acc[4][8][4];
#pragma unroll
    for (int i = 0; i < 4; i++)
#pragma unroll
        for (int j = 0; j < 8; j++)
#pragma unroll
            for (int r = 0; r < 4; r++) acc[i][j][r] = 0.f;

    // ---- producer: fill one stage (A 128x64 | B 256x64 bf16) ----
    auto fill = [&](int kt, int st) {
        const uint32_t stb = sbase + st * STAGE_BYTES;
        const __nv_bfloat16* Ak = A + (size_t)m0 * K + (size_t)kt * 64;
        const __nv_bfloat16* Bk = Bm + (size_t)n0 * K + (size_t)kt * 64;
#pragma unroll
        for (int i = 0; i < 4; i++) {              // A: 1024 16B chunks
            int q = t + i * 256;
            int row = q >> 3, ch = q & 7;
            uint32_t dst = stb + row * SROWB + ch * 16;
            const void* gp = Ak + (size_t)row * K + ch * 8;
            asm volatile("cp.async.cg.shared.global [%0], [%1], 16;\n" ::"r"(dst), "l"(gp));
        }
#pragma unroll
        for (int i = 0; i < 8; i++) {              // B: 2048 16B chunks
            int q = t + i * 256;
            int row = q >> 3, ch = q & 7;
            uint32_t dst = stb + A_BYTES + row * SROWB + ch * 16;
            const void* gp = Bk + (size_t)row * K + ch * 8;
            asm volatile("cp.async.cg.shared.global [%0], [%1], 16;\n" ::"r"(dst), "l"(gp));
        }
    };

    fill(0, 0);
    asm volatile("cp.async.commit_group;\n" ::);
    if (KT > 1) fill(1, 1);
    asm volatile("cp.async.commit_group;\n" ::);

    for (int kt = 0; kt < KT; ++kt) {
        const int nf = kt + 2;
        if (nf < KT) fill(nf, nf % 3);
        asm volatile("cp.async.commit_group;\n" ::);
        asm volatile("cp.async.wait_group 2;\n" ::);
        __syncthreads();

        const uint32_t stb = sbase + (kt % 3) * STAGE_BYTES;
        const uint32_t aB = stb;
        const uint32_t bB = stb + A_BYTES;
#pragma unroll
        for (int ks = 0; ks < 4; ++ks) {
            uint32_t af[4][4], bf[4][4];
#pragma unroll
            for (int i = 0; i < 4; i++) {
                uint32_t addr = aB + (uint32_t)((wm + i * 16 + (lane & 15)) * SROWB +
                                                (ks * 16 + (lane >> 4) * 8) * 2);
                asm volatile("ldmatrix.sync.aligned.m8n8.x4.shared.b16 {%0,%1,%2,%3}, [%4];\n"
                             : "=r"(af[i][0]), "=r"(af[i][1]), "=r"(af[i][2]), "=r"(af[i][3])
                             : "r"(addr));
            }
#pragma unroll
            for (int jj = 0; jj < 4; jj++) {
                uint32_t addr = bB + (uint32_t)((wn + jj * 16 + (lane & 15)) * SROWB +
                                                (ks * 16 + (lane >> 4) * 8) * 2);
                asm volatile("ldmatrix.sync.aligned.m8n8.x4.shared.b16 {%0,%1,%2,%3}, [%4];\n"
                             : "=r"(bf[jj][0]), "=r"(bf[jj][1]), "=r"(bf[jj][2]), "=r"(bf[jj][3])
                             : "r"(addr));
            }
#pragma unroll
            for (int i = 0; i < 4; i++) {
#pragma unroll
                for (int j = 0; j < 8; j++) {
                    const int jj = j >> 1, s = j & 1;
                    asm volatile(
                        "mma.sync.aligned.m16n8k16.row.col.f32.bf16.bf16.f32 "
                        "{%0,%1,%2,%3}, {%4,%5,%6,%7}, {%8,%9}, {%0,%1,%2,%3};\n"
                        : "+f"(acc[i][j][0]), "+f"(acc[i][j][1]),
                          "+f"(acc[i][j][2]), "+f"(acc[i][j][3])
                        : "r"(af[i][0]), "r"(af[i][1]), "r"(af[i][2]), "r"(af[i][3]),
                          "r"(bf[jj][s]), "r"(bf[jj][s + 2]));
                }
            }
        }
        __syncthreads();
    }

    // ----- epilogue -----
#pragma unroll
    for (int i = 0; i < 4; i++) {
        int row0 = m0 + wm + i * 16 + (lane >> 2);
#pragma unroll
        for (int j = 0; j < 8; j++) {
            int col = n0 + wn + j * 8 + (lane & 3) * 2;
#pragma unroll
            for (int h = 0; h < 2; h++) {
                int r = row0 + h * 8;
                float v0 = acc[i][j][h * 2 + 0];
                float v1 = acc[i][j][h * 2 + 1];
                size_t off = (size_t)r * N + col;
                if (EPI == 0) {
                    *(float2*)((float*)Cv + off) = make_float2(v0, v1);
                } else if (EPI == 1) {
                    *(__nv_bfloat162*)((__nv_bfloat16*)Cv + off) =
                        __floats2bfloat162_rn(v0, v1);
                } else if (EPI == 2) {
                    float x0 = v0 + bias[col], x1 = v1 + bias[col + 1];
                    float g0 = 0.5f * x0 * (1.f + erff(x0 * 0.70710678118654752f));
                    float g1 = 0.5f * x1 * (1.f + erff(x1 * 0.70710678118654752f));
                    *(__nv_bfloat162*)((__nv_bfloat16*)Cv + off) =
                        __floats2bfloat162_rn(g0, g1);
                } else {
                    float x0 = v0 + bias[col], x1 = v1 + bias[col + 1];
                    float s0 = 1.f / (1.f + expf(-x0));
                    float s1 = 1.f / (1.f + expf(-x1));
                    __nv_bfloat162 cc = *(const __nv_bfloat162*)(crossp + off);
                    float2 hv = *(const float2*)(hid + off);
                    *(float2*)((float*)Cv + off) =
                        make_float2(hv.x + s0 * __bfloat162float(cc.x),
                                    hv.y + s1 * __bfloat162float(cc.y));
                }
            }
        }
    }
}

// ---------------- host launcher ----------------
extern "C" void kernel_launch(void* const* d_in, const int* in_sizes, int n_in,
                              void* d_out, int out_size) {
    (void)in_sizes; (void)n_in; (void)out_size;
    const float* hidden = (const float*)d_in[0];
    const void*  amask  = d_in[1];
    const float* Wsim   = (const float*)d_in[2];
    const float* Wval   = (const float*)d_in[3];
    const float* Wg1    = (const float*)d_in[4];
    const float* bg1    = (const float*)d_in[5];
    const float* Wg2    = (const float*)d_in[6];
    const float* bg2    = (const float*)d_in[7];
    float* out = (float*)d_out;

    __nv_bfloat16 *hbf, *wsim, *wval, *wg1, *wg2, *proj, *vals, *valsT, *wts, *cross, *gin, *h1;
    float* sim;
    unsigned char* mask;
    cudaGetSymbolAddress((void**)&hbf,   g_hidden_bf);
    cudaGetSymbolAddress((void**)&wsim,  g_Wsim_bf);
    cudaGetSymbolAddress((void**)&wval,  g_Wval_bf);
    cudaGetSymbolAddress((void**)&wg1,   g_Wg1_bf);
    cudaGetSymbolAddress((void**)&wg2,   g_Wg2_bf);
    cudaGetSymbolAddress((void**)&proj,  g_proj_bf);
    cudaGetSymbolAddress((void**)&vals,  g_values_bf);
    cudaGetSymbolAddress((void**)&valsT, g_valuesT_bf);
    cudaGetSymbolAddress((void**)&sim,   g_sim_f32);
    cudaGetSymbolAddress((void**)&wts,   g_weights_bf);
    cudaGetSymbolAddress((void**)&cross, g_cross_bf);
    cudaGetSymbolAddress((void**)&gin,   g_gatein_bf);
    cudaGetSymbolAddress((void**)&h1,    g_h1_bf);
    cudaGetSymbolAddress((void**)&mask,  g_mask_u8);

    cudaFuncSetAttribute(gemm_nt_kernel<0>, cudaFuncAttributeMaxDynamicSharedMemorySize, GEMM_DYN_SMEM);
    cudaFuncSetAttribute(gemm_nt_kernel<1>, cudaFuncAttributeMaxDynamicSharedMemorySize, GEMM_DYN_SMEM);
    cudaFuncSetAttribute(gemm_nt_kernel<2>, cudaFuncAttributeMaxDynamicSharedMemorySize, GEMM_DYN_SMEM);
    cudaFuncSetAttribute(gemm_nt_kernel<3>, cudaFuncAttributeMaxDynamicSharedMemorySize, GEMM_DYN_SMEM);

    detect_mask_kernel<<<1, 256>>>((const unsigned char*)amask);
    expand_mask_kernel<<<(BB + 255) / 256, 256>>>(amask, mask);

    {
        long n2;
        n2 = (long)BB * HH / 2;
        f32_to_bf16_kernel<<<(unsigned)((n2 + 255) / 256), 256>>>(hidden, hbf, n2);
        n2 = (long)HH * HH / 2;
        f32_to_bf16_kernel<<<(unsigned)((n2 + 255) / 256), 256>>>(Wsim, wsim, n2);
        f32_to_bf16_kernel<<<(unsigned)((n2 + 255) / 256), 256>>>(Wval, wval, n2);
        n2 = (long)GHH * 2 * HH / 2;
        f32_to_bf16_kernel<<<(unsigned)((n2 + 255) / 256), 256>>>(Wg1, wg1, n2);
        n2 = (long)HH * GHH / 2;
        f32_to_bf16_kernel<<<(unsigned)((n2 + 255) / 256), 256>>>(Wg2, wg2, n2);
    }

    // 1) proj = hidden @ Wsim^T (bf16)
    gemm_nt_kernel<1><<<dim3(HH / 256, BB / 128), 256, GEMM_DYN_SMEM>>>(
        hbf, wsim, proj, BB, HH, HH, nullptr, nullptr, nullptr);
    // 2) normalize
    normalize_rows_kernel<<<BB, 256>>>(proj);
    // 3) sim = normed @ normed^T (f32)
    gemm_nt_kernel<0><<<dim3(BB / 256, BB / 128), 256, GEMM_DYN_SMEM>>>(
        proj, proj, sim, BB, BB, HH, nullptr, nullptr, nullptr);
    // 4) softmax
    softmax_mask_kernel<<<BB, 256>>>(sim, mask, wts);
    // 5) values = hidden @ Wval^T (bf16)
    gemm_nt_kernel<1><<<dim3(HH / 256, BB / 128), 256, GEMM_DYN_SMEM>>>(
        hbf, wval, vals, BB, HH, HH, nullptr, nullptr, nullptr);
    // 6) transpose
    transpose_bf16_kernel<<<dim3(HH / 32, BB / 32), dim3(32, 8)>>>(vals, valsT, BB, HH);
    // 7) cross = weights @ values (bf16)
    gemm_nt_kernel<1><<<dim3(HH / 256, BB / 128), 256, GEMM_DYN_SMEM>>>(
        wts, valsT, cross, BB, HH, BB, nullptr, nullptr, nullptr);
    // 8) concat
    concat_kernel<<<(unsigned)(((long)BB * 2 * HH / 4 + 255) / 256), 256>>>(hbf, cross, gin);
    // 9) h1 = gelu(gate_in @ Wg1^T + b1) (bf16)
    gemm_nt_kernel<2><<<dim3(GHH / 256, BB / 128), 256, GEMM_DYN_SMEM>>>(
        gin, wg1, h1, BB, GHH, 2 * HH, bg1, nullptr, nullptr);
    // 10) out = hidden + sigmoid(h1 @ Wg2^T + b2) * cross (f32)
    gemm_nt_kernel<3><<<dim3(HH / 256, BB / 128), 256, GEMM_DYN_SMEM>>>(
        h1, wg2, out, BB, HH, GHH, bg2, hidden, cross);
}

// round 5
// speedup vs baseline: 1.0722x; 1.0206x over previous
#include <cuda_runtime.h>
#include <cuda_bf16.h>
#include <cuda_fp8.h>
#include <cstdint>
#include <math.h>

#define BB 8192
#define HH 4096
#define GHH 1024

// ---------------- scratch (device globals; allocation-free rule) ----------------
__device__ uint8_t       g_hidden8[(size_t)BB * HH];
__device__ uint8_t       g_Wsim8[(size_t)HH * HH];
__device__ uint8_t       g_Wval8[(size_t)HH * HH];
__device__ uint8_t       g_Wg18[(size_t)GHH * 2 * HH];
__device__ uint8_t       g_Wg28[(size_t)HH * GHH];
__device__ __nv_bfloat16 g_proj_bf[(size_t)BB * HH];
__device__ uint8_t       g_normed8[(size_t)BB * HH];
__device__ uint8_t       g_values8[(size_t)BB * HH];
__device__ uint8_t       g_valuesT8[(size_t)HH * BB];
__device__ float         g_sim_f32[(size_t)BB * BB];
__device__ uint8_t       g_weights8[(size_t)BB * BB];
__device__ __nv_bfloat16 g_cross_bf[(size_t)BB * HH];
__device__ uint8_t       g_gatein8[(size_t)BB * 2 * HH];
__device__ uint8_t       g_h18[(size_t)BB * GHH];
__device__ unsigned char g_mask_u8[BB];
__device__ int           g_mask_code;

// scales: hidden x16, W x256, normed x64, weights x65536, values x16, cross(gatein) x16, h1 x64

// ---------------- helpers ----------------
__device__ __forceinline__ uint32_t smem_u32(const void* p) {
    return (uint32_t)__cvta_generic_to_shared(p);
}
__device__ __forceinline__ uint8_t f2e4m3(float v) {
    return (uint8_t)__nv_cvt_float_to_fp8(v, __NV_SATFINITE, __NV_E4M3);
}

// ---------------- mask dtype sniffing ----------------
__global__ void detect_mask_kernel(const unsigned char* m) {
    __shared__ int s_nonbin, s_off4, s_fbad, s_bfbad;
    if (threadIdx.x == 0) { s_nonbin = 0; s_off4 = 0; s_fbad = 0; s_bfbad = 0; }
    __syncthreads();
    int nonbin = 0, off4 = 0, fbad = 0, bfbad = 0;
    for (int j = threadIdx.x; j < 8192; j += 256) {
        unsigned char b = m[j];
        if (b > 1) nonbin++;
        if ((j & 3) != 0 && b != 0) off4++;
    }
    const uint32_t* u = (const uint32_t*)m;
    for (int i = threadIdx.x; i < 2048; i += 256) {
        uint32_t w = u[i];
        if (!(w == 0u || w == 0x3f800000u)) fbad++;
    }
    const uint16_t* h = (const uint16_t*)m;
    for (int i = threadIdx.x; i < 4096; i += 256) {
        uint16_t x = h[i];
        if (!(x == 0 || x == 0x3f80)) bfbad++;
    }
    atomicAdd(&s_nonbin, nonbin);
    atomicAdd(&s_off4, off4);
    atomicAdd(&s_fbad, fbad);
    atomicAdd(&s_bfbad, bfbad);
    __syncthreads();
    if (threadIdx.x == 0) {
        int code;
        if (s_nonbin == 0) code = (s_off4 > 0) ? 0 : 1;
        else if (s_fbad == 0) code = 2;
        else if (s_bfbad == 0) code = 3;
        else code = 1;
        g_mask_code = code;
    }
}

__global__ void expand_mask_kernel(const void* m, unsigned char* out) {
    int i = blockIdx.x * blockDim.x + threadIdx.x;
    if (i >= BB) return;
    int code = g_mask_code;
    bool v;
    if (code == 0)      v = ((const unsigned char*)m)[i] != 0;
    else if (code == 1) v = ((const int*)m)[i] != 0;
    else if (code == 2) v = ((const float*)m)[i] != 0.0f;
    else                v = (((const uint16_t*)m)[i] & 0x7fff) != 0;
    out[i] = v ? 1 : 0;
}

// ---------------- fp32 -> fp8 convert (scale) ----------------
__global__ void f32_to_fp8_kernel(const float* __restrict__ in,
                                  uint8_t* __restrict__ out, float scale, long n4) {
    long i = (long)blockIdx.x * blockDim.x + threadIdx.x;
    if (i < n4) {
        float4 v = ((const float4*)in)[i];
        uint32_t p = (uint32_t)f2e4m3(v.x * scale) |
                     ((uint32_t)f2e4m3(v.y * scale) << 8) |
                     ((uint32_t)f2e4m3(v.z * scale) << 16) |
                     ((uint32_t)f2e4m3(v.w * scale) << 24);
        ((uint32_t*)out)[i] = p;
    }
}

// hidden -> g_hidden8 AND first half of g_gatein8, scale 16
__global__ void hidden_to_fp8_kernel(const float* __restrict__ in,
                                     uint8_t* __restrict__ out,
                                     uint8_t* __restrict__ gatein) {
    long i = ((long)blockIdx.x * blockDim.x + threadIdx.x);
    if (i >= (long)BB * HH / 4) return;
    float4 v = ((const float4*)in)[i];
    uint32_t p = (uint32_t)f2e4m3(v.x * 16.f) |
                 ((uint32_t)f2e4m3(v.y * 16.f) << 8) |
                 ((uint32_t)f2e4m3(v.z * 16.f) << 16) |
                 ((uint32_t)f2e4m3(v.w * 16.f) << 24);
    ((uint32_t*)out)[i] = p;
    long e = i * 4;
    long b = e >> 12;            // /HH
    int  j = (int)(e & (HH - 1));
    *(uint32_t*)(gatein + b * (2 * HH) + j) = p;
}

// ---------------- row L2 normalize: bf16 proj -> fp8 normed (x64) ----------------
__global__ void normalize_rows_kernel(const __nv_bfloat16* __restrict__ p,
                                      uint8_t* __restrict__ normed) {
    int row = blockIdx.x;
    const __nv_bfloat16* r = p + (size_t)row * HH;
    float s = 0.f;
    for (int j = threadIdx.x; j < HH; j += 256) {
        float v = __bfloat162float(r[j]);
        s += v * v;
    }
#pragma unroll
    for (int o = 16; o > 0; o >>= 1) s += __shfl_xor_sync(0xffffffffu, s, o);
    __shared__ float ws[8];
    int w = threadIdx.x >> 5, l = threadIdx.x & 31;
    if (l == 0) ws[w] = s;
    __syncthreads();
    if (threadIdx.x < 32) {
        float x = (threadIdx.x < 8) ? ws[threadIdx.x] : 0.f;
#pragma unroll
        for (int o = 4; o > 0; o >>= 1) x += __shfl_xor_sync(0xffffffffu, x, o);
        if (threadIdx.x == 0) ws[0] = x;
    }
    __syncthreads();
    float scale = 64.f / fmaxf(sqrtf(ws[0]), 1e-12f);
    uint8_t* nr = normed + (size_t)row * HH;
    for (int j = threadIdx.x; j < HH / 4; j += 256) {
        float v0 = __bfloat162float(r[j * 4 + 0]) * scale;
        float v1 = __bfloat162float(r[j * 4 + 1]) * scale;
        float v2 = __bfloat162float(r[j * 4 + 2]) * scale;
        float v3 = __bfloat162float(r[j * 4 + 3]) * scale;
        ((uint32_t*)nr)[j] = (uint32_t)f2e4m3(v0) | ((uint32_t)f2e4m3(v1) << 8) |
                             ((uint32_t)f2e4m3(v2) << 16) | ((uint32_t)f2e4m3(v3) << 24);
    }
}

// ---------------- masked softmax: f32 sim -> fp8 weights (x65536) ----------------
__global__ void softmax_mask_kernel(const float* __restrict__ sim,
                                    const unsigned char* __restrict__ mask,
                                    uint8_t* __restrict__ wts) {
    int row = blockIdx.x;
    __shared__ float sv[BB];
    __shared__ float red[8];
    const float* sr = sim + (size_t)row * BB;
    float mx = -INFINITY;
    for (int j = threadIdx.x; j < BB; j += 256) {
        float v = sr[j];
        if (j == row || mask[j] == 0) v = -INFINITY;
        sv[j] = v;
        mx = fmaxf(mx, v);
    }
#pragma unroll
    for (int o = 16; o > 0; o >>= 1) mx = fmaxf(mx, __shfl_xor_sync(0xffffffffu, mx, o));
    int w = threadIdx.x >> 5, l = threadIdx.x & 31;
    if (l == 0) red[w] = mx;
    __syncthreads();
    if (threadIdx.x < 32) {
        float x = (threadIdx.x < 8) ? red[threadIdx.x] : -INFINITY;
#pragma unroll
        for (int o = 4; o > 0; o >>= 1) x = fmaxf(x, __shfl_xor_sync(0xffffffffu, x, o));
        if (threadIdx.x == 0) red[0] = x;
    }
    __syncthreads();
    float M = red[0];
    __syncthreads();
    float sum = 0.f;
    for (int j = threadIdx.x; j < BB; j += 256) {
        float v = sv[j];
        float e = (v == -INFINITY) ? 0.f : __expf(v - M);
        sv[j] = e;
        sum += e;
    }
#pragma unroll
    for (int o = 16; o > 0; o >>= 1) sum += __shfl_xor_sync(0xffffffffu, sum, o);
    if (l == 0) red[w] = sum;
    __syncthreads();
    if (threadIdx.x < 32) {
        float x = (threadIdx.x < 8) ? red[threadIdx.x] : 0.f;
#pragma unroll
        for (int o = 4; o > 0; o >>= 1) x += __shfl_xor_sync(0xffffffffu, x, o);
        if (threadIdx.x == 0) red[0] = x;
    }
    __syncthreads();
    float S = red[0];
    float inv = (S > 0.f) ? 65536.f / S : 0.f;
    uint8_t* wr = wts + (size_t)row * BB;
    for (int j = threadIdx.x; j < BB / 4; j += 256) {
        ((uint32_t*)wr)[j] = (uint32_t)f2e4m3(sv[j * 4 + 0] * inv) |
                             ((uint32_t)f2e4m3(sv[j * 4 + 1] * inv) << 8) |
                             ((uint32_t)f2e4m3(sv[j * 4 + 2] * inv) << 16) |
                             ((uint32_t)f2e4m3(sv[j * 4 + 3] * inv) << 24);
    }
}

// ---------------- u8 transpose (values -> valuesT) ----------------
__global__ void transpose_u8_kernel(const uint8_t* __restrict__ in,
                                    uint8_t* __restrict__ out, int R, int C) {
    __shared__ uint8_t tile[32][33];
    int x = blockIdx.x * 32 + threadIdx.x;
    int y0 = blockIdx.y * 32 + threadIdx.y;
#pragma unroll
    for (int i = 0; i < 32; i += 8)
        tile[threadIdx.y + i][threadIdx.x] = in[(size_t)(y0 + i) * C + x];
    __syncthreads();
    int x2 = blockIdx.y * 32 + threadIdx.x;
    int y2 = blockIdx.x * 32 + threadIdx.y;
#pragma unroll
    for (int i = 0; i < 32; i += 8)
        out[(size_t)(y2 + i) * R + x2] = tile[threadIdx.x][threadIdx.y + i];
}

// ================= fp8 NT GEMM (mma.sync m16n8k32 e4m3): C = A * B^T =========
// CTA tile 128x256, warp tile 64x64 (8 warps 2Mx4N), K-stage 128 elements,
// 3-stage cp.async pipeline, smem row stride 144B.
// EPI: 0=f32(desc), 1=bf16(desc), 2=fp8(desc*oscale),
//      3=cross: bf16 + fp8 into gatein second half,
//      4=gelu(desc*acc+bias)->fp8, 5=hid+sigmoid(desc*acc+bias)*cross->f32
#define SROWB 144
#define A_BYTES (128 * SROWB)
#define B_BYTES (256 * SROWB)
#define STAGE_BYTES (A_BYTES + B_BYTES)
#define GEMM_DYN_SMEM (3 * STAGE_BYTES + 256)

template <int EPI>
__global__ void __launch_bounds__(256, 1)
gemm_nt_fp8(const uint8_t* __restrict__ A,
            const uint8_t* __restrict__ Bm,
            void* __restrict__ Cv,
            int M, int N, int K,
            float desc, float oscale,
            const float* __restrict__ bias,
            const float* __restrict__ hid,
            const __nv_bfloat16* __restrict__ crossp,
            uint8_t* __restrict__ out2) {
    extern __shared__ char dynsm[];
    const uint32_t sbase = (smem_u32(dynsm) + 127u) & ~127u;

    const int t = threadIdx.x;
    const int warp = t >> 5, lane = t & 31;
    const int wm = (warp & 1) * 64;
    const int wn = (warp >> 1) * 64;
    const int m0 = blockIdx.y * 128;
    const int n0 = blockIdx.x * 256;
    const int KT = K >> 7;                 // 128-element K stages

    float acc[4][8][4];
#pragma unroll
    for (int i = 0; i < 4; i++)
#pragma unroll
        for (int j = 0; j < 8; j++)
#pragma unroll
            for (int r = 0; r < 4; r++) acc[i][j][r] = 0.f;

    auto fill = [&](int kt, int st) {
        const uint32_t stb = sbase + st * STAGE_BYTES;
        const uint8_t* Ak = A + (size_t)m0 * K + (size_t)kt * 128;
        const uint8_t* Bk = Bm + (size_t)n0 * K + (size_t)kt * 128;
#pragma unroll
        for (int i = 0; i < 4; i++) {              // A: 128 rows x 128B
            int q = t + i * 256;
            int row = q >> 3, ch = q & 7;
            uint32_t dst = stb + row * SROWB + ch * 16;
            const void* gp = Ak + (size_t)row * K + ch * 16;
            asm volatile("cp.async.cg.shared.global [%0], [%1], 16;\n" ::"r"(dst), "l"(gp));
        }
#pragma unroll
        for (int i = 0; i < 8; i++) {              // B: 256 rows x 128B
            int q = t + i * 256;
            int row = q >> 3, ch = q & 7;
            uint32_t dst = stb + A_BYTES + row * SROWB + ch * 16;
            const void* gp = Bk + (size_t)row * K + ch * 16;
            asm volatile("cp.async.cg.shared.global [%0], [%1], 16;\n" ::"r"(dst), "l"(gp));
        }
    };

    fill(0, 0);
    asm volatile("cp.async.commit_group;\n" ::);
    if (KT > 1) fill(1, 1);
    asm volatile("cp.async.commit_group;\n" ::);

    for (int kt = 0; kt < KT; ++kt) {
        const int nf = kt + 2;
        if (nf < KT) fill(nf, nf % 3);
        asm volatile("cp.async.commit_group;\n" ::);
        asm volatile("cp.async.wait_group 2;\n" ::);
        __syncthreads();

        const uint32_t stb = sbase + (kt % 3) * STAGE_BYTES;
        const uint32_t aB = stb;
        const uint32_t bB = stb + A_BYTES;
#pragma unroll
        for (int ks = 0; ks < 4; ++ks) {           // k32 steps within 128-elem stage
            uint32_t af[4][4], bf[4][4];
#pragma unroll
            for (int i = 0; i < 4; i++) {
                uint32_t addr = aB + (uint32_t)((wm + i * 16 + (lane & 15)) * SROWB +
                                                ks * 32 + (lane >> 4) * 16);
                asm volatile("ldmatrix.sync.aligned.m8n8.x4.shared.b16 {%0,%1,%2,%3}, [%4];\n"
                             : "=r"(af[i][0]), "=r"(af[i][1]), "=r"(af[i][2]), "=r"(af[i][3])
                             : "r"(addr));
            }
#pragma unroll
            for (int jj = 0; jj < 4; jj++) {
                uint32_t addr = bB + (uint32_t)((wn + jj * 16 + (lane & 15)) * SROWB +
                                                ks * 32 + (lane >> 4) * 16);
                asm volatile("ldmatrix.sync.aligned.m8n8.x4.shared.b16 {%0,%1,%2,%3}, [%4];\n"
                             : "=r"(bf[jj][0]), "=r"(bf[jj][1]), "=r"(bf[jj][2]), "=r"(bf[jj][3])
                             : "r"(addr));
            }
#pragma unroll
            for (int i = 0; i < 4; i++) {
#pragma unroll
                for (int j = 0; j < 8; j++) {
                    const int jj = j >> 1, s = j & 1;
                    asm volatile(
                        "mma.sync.aligned.m16n8k32.row.col.f32.e4m3.e4m3.f32 "
                        "{%0,%1,%2,%3}, {%4,%5,%6,%7}, {%8,%9}, {%0,%1,%2,%3};\n"
                        : "+f"(acc[i][j][0]), "+f"(acc[i][j][1]),
                          "+f"(acc[i][j][2]), "+f"(acc[i][j][3])
                        : "r"(af[i][0]), "r"(af[i][1]), "r"(af[i][2]), "r"(af[i][3]),
                          "r"(bf[jj][s]), "r"(bf[jj][s + 2]));
                }
            }
        }
        __syncthreads();
    }

    // ----- epilogue -----
#pragma unroll
    for (int i = 0; i < 4; i++) {
        int row0 = m0 + wm + i * 16 + (lane >> 2);
#pragma unroll
        for (int j = 0; j < 8; j++) {
            int col = n0 + wn + j * 8 + (lane & 3) * 2;
#pragma unroll
            for (int h = 0; h < 2; h++) {
                int r = row0 + h * 8;
                float v0 = acc[i][j][h * 2 + 0] * desc;
                float v1 = acc[i][j][h * 2 + 1] * desc;
                size_t off = (size_t)r * N + col;
                if (EPI == 0) {
                    *(float2*)((float*)Cv + off) = make_float2(v0, v1);
                } else if (EPI == 1) {
                    *(__nv_bfloat162*)((__nv_bfloat16*)Cv + off) =
                        __floats2bfloat162_rn(v0, v1);
                } else if (EPI == 2) {
                    uint16_t p = (uint16_t)f2e4m3(v0 * oscale) |
                                 ((uint16_t)f2e4m3(v1 * oscale) << 8);
                    *(uint16_t*)((uint8_t*)Cv + off) = p;
                } else if (EPI == 3) {
                    *(__nv_bfloat162*)((__nv_bfloat16*)Cv + off) =
                        __floats2bfloat162_rn(v0, v1);
                    uint16_t p = (uint16_t)f2e4m3(v0 * oscale) |
                                 ((uint16_t)f2e4m3(v1 * oscale) << 8);
                    *(uint16_t*)(out2 + (size_t)r * (2 * HH) + HH + col) = p;
                } else if (EPI == 4) {
                    float x0 = v0 + bias[col], x1 = v1 + bias[col + 1];
                    float g0 = 0.5f * x0 * (1.f + erff(x0 * 0.70710678118654752f));
                    float g1 = 0.5f * x1 * (1.f + erff(x1 * 0.70710678118654752f));
                    uint16_t p = (uint16_t)f2e4m3(g0 * oscale) |
                                 ((uint16_t)f2e4m3(g1 * oscale) << 8);
                    *(uint16_t*)((uint8_t*)Cv + off) = p;
                } else {
                    float x0 = v0 + bias[col], x1 = v1 + bias[col + 1];
                    float s0 = 1.f / (1.f + expf(-x0));
                    float s1 = 1.f / (1.f + expf(-x1));
                    __nv_bfloat162 cc = *(const __nv_bfloat162*)(crossp + off);
                    float2 hv = *(const float2*)(hid + off);
                    *(float2*)((float*)Cv + off) =
                        make_float2(hv.x + s0 * __bfloat162float(cc.x),
                                    hv.y + s1 * __bfloat162float(cc.y));
                }
            }
        }
    }
}

// ---------------- host launcher ----------------
extern "C" void kernel_launch(void* const* d_in, const int* in_sizes, int n_in,
                              void* d_out, int out_size) {
    (void)in_sizes; (void)n_in; (void)out_size;
    const float* hidden = (const float*)d_in[0];
    const void*  amask  = d_in[1];
    const float* Wsim   = (const float*)d_in[2];
    const float* Wval   = (const float*)d_in[3];
    const float* Wg1    = (const float*)d_in[4];
    const float* bg1    = (const float*)d_in[5];
    const float* Wg2    = (const float*)d_in[6];
    const float* bg2    = (const float*)d_in[7];
    float* out = (float*)d_out;

    uint8_t *h8, *wsim8, *wval8, *wg18, *wg28, *normed8, *vals8, *valsT8, *wts8, *gin8, *h18;
    __nv_bfloat16 *proj, *cross;
    float* sim;
    unsigned char* mask;
    cudaGetSymbolAddress((void**)&h8,      g_hidden8);
    cudaGetSymbolAddress((void**)&wsim8,   g_Wsim8);
    cudaGetSymbolAddress((void**)&wval8,   g_Wval8);
    cudaGetSymbolAddress((void**)&wg18,    g_Wg18);
    cudaGetSymbolAddress((void**)&wg28,    g_Wg28);
    cudaGetSymbolAddress((void**)&proj,    g_proj_bf);
    cudaGetSymbolAddress((void**)&normed8, g_normed8);
    cudaGetSymbolAddress((void**)&vals8,   g_values8);
    cudaGetSymbolAddress((void**)&valsT8,  g_valuesT8);
    cudaGetSymbolAddress((void**)&sim,     g_sim_f32);
    cudaGetSymbolAddress((void**)&wts8,    g_weights8);
    cudaGetSymbolAddress((void**)&cross,   g_cross_bf);
    cudaGetSymbolAddress((void**)&gin8,    g_gatein8);
    cudaGetSymbolAddress((void**)&h18,     g_h18);
    cudaGetSymbolAddress((void**)&mask,    g_mask_u8);

    cudaFuncSetAttribute(gemm_nt_fp8<0>, cudaFuncAttributeMaxDynamicSharedMemorySize, GEMM_DYN_SMEM);
    cudaFuncSetAttribute(gemm_nt_fp8<1>, cudaFuncAttributeMaxDynamicSharedMemorySize, GEMM_DYN_SMEM);
    cudaFuncSetAttribute(gemm_nt_fp8<2>, cudaFuncAttributeMaxDynamicSharedMemorySize, GEMM_DYN_SMEM);
    cudaFuncSetAttribute(gemm_nt_fp8<3>, cudaFuncAttributeMaxDynamicSharedMemorySize, GEMM_DYN_SMEM);
    cudaFuncSetAttribute(gemm_nt_fp8<4>, cudaFuncAttributeMaxDynamicSharedMemorySize, GEMM_DYN_SMEM);
    cudaFuncSetAttribute(gemm_nt_fp8<5>, cudaFuncAttributeMaxDynamicSharedMemorySize, GEMM_DYN_SMEM);

    detect_mask_kernel<<<1, 256>>>((const unsigned char*)amask);
    expand_mask_kernel<<<(BB + 255) / 256, 256>>>(amask, mask);

    // converts (scales: hidden x16, weights x256)
    hidden_to_fp8_kernel<<<(unsigned)(((long)BB * HH / 4 + 255) / 256), 256>>>(hidden, h8, gin8);
    {
        long n4 = (long)HH * HH / 4;
        f32_to_fp8_kernel<<<(unsigned)((n4 + 255) / 256), 256>>>(Wsim, wsim8, 256.f, n4);
        f32_to_fp8_kernel<<<(unsigned)((n4 + 255) / 256), 256>>>(Wval, wval8, 256.f, n4);
        n4 = (long)GHH * 2 * HH / 4;
        f32_to_fp8_kernel<<<(unsigned)((n4 + 255) / 256), 256>>>(Wg1, wg18, 256.f, n4);
        n4 = (long)HH * GHH / 4;
        f32_to_fp8_kernel<<<(unsigned)((n4 + 255) / 256), 256>>>(Wg2, wg28, 256.f, n4);
    }

    // 1) proj = hidden @ Wsim^T -> bf16   (desc 1/(16*256))
    gemm_nt_fp8<1><<<dim3(HH / 256, BB / 128), 256, GEMM_DYN_SMEM>>>(
        h8, wsim8, proj, BB, HH, HH, 1.f / 4096.f, 0.f, nullptr, nullptr, nullptr, nullptr);
    // 2) normalize -> normed fp8 (x64)
    normalize_rows_kernel<<<BB, 256>>>(proj, normed8);
    // 3) sim = normed @ normed^T -> f32   (desc 1/(64*64))
    gemm_nt_fp8<0><<<dim3(BB / 256, BB / 128), 256, GEMM_DYN_SMEM>>>(
        normed8, normed8, sim, BB, BB, HH, 1.f / 4096.f, 0.f, nullptr, nullptr, nullptr, nullptr);
    // 4) softmax -> weights fp8 (x65536)
    softmax_mask_kernel<<<BB, 256>>>(sim, mask, wts8);
    // 5) values = hidden @ Wval^T -> fp8 (x16)
    gemm_nt_fp8<2><<<dim3(HH / 256, BB / 128), 256, GEMM_DYN_SMEM>>>(
        h8, wval8, vals8, BB, HH, HH, 1.f / 4096.f, 16.f, nullptr, nullptr, nullptr, nullptr);
    // 6) transpose values -> valuesT
    transpose_u8_kernel<<<dim3(HH / 32, BB / 32), dim3(32, 8)>>>(vals8, valsT8, BB, HH);
    // 7) cross = weights @ values -> bf16 + fp8(x16) into gatein[:, H:2H]
    gemm_nt_fp8<3><<<dim3(HH / 256, BB / 128), 256, GEMM_DYN_SMEM>>>(
        wts8, valsT8, cross, BB, HH, BB, 1.f / 1048576.f, 16.f, nullptr, nullptr, nullptr, gin8);
    // 8) h1 = gelu(gatein @ Wg1^T + b1) -> fp8 (x64)   (desc 1/(16*256))
    gemm_nt_fp8<4><<<dim3(GHH / 256, BB / 128), 256, GEMM_DYN_SMEM>>>(
        gin8, wg18, h18, BB, GHH, 2 * HH, 1.f / 4096.f, 64.f, bg1, nullptr, nullptr, nullptr);
    // 9) out = hidden + sigmoid(h1 @ Wg2^T + b2) * cross   (desc 1/(64*256))
    gemm_nt_fp8<5><<<dim3(HH / 256, BB / 128), 256, GEMM_DYN_SMEM>>>(
        h18, wg28, out, BB, HH, GHH, 1.f / 16384.f, 0.f, bg2, hidden, cross, nullptr);
}

// round 6
// speedup vs baseline: 1.1600x; 1.0819x over previous
#include <cuda_runtime.h>
#include <cuda_bf16.h>
#include <cuda_fp8.h>
#include <cstdint>
#include <math.h>

#define BB 8192
#define HH 4096
#define GHH 1024

// ---------------- scratch (device globals; allocation-free rule) ----------------
__device__ uint8_t       g_hidden8[(size_t)BB * HH];
__device__ uint8_t       g_Wsim8[(size_t)HH * HH];
__device__ uint8_t       g_Wval8[(size_t)HH * HH];
__device__ uint8_t       g_Wg18[(size_t)GHH * 2 * HH];
__device__ uint8_t       g_Wg28[(size_t)HH * GHH];
__device__ __nv_bfloat16 g_proj_bf[(size_t)BB * HH];
__device__ uint8_t       g_normed8[(size_t)BB * HH];
__device__ uint8_t       g_values8[(size_t)BB * HH];
__device__ uint8_t       g_valuesT8[(size_t)HH * BB];
__device__ float         g_sim_f32[(size_t)BB * BB];
__device__ uint8_t       g_weights8[(size_t)BB * BB];
__device__ __nv_bfloat16 g_cross_bf[(size_t)BB * HH];
__device__ uint8_t       g_gatein8[(size_t)BB * 2 * HH];
__device__ uint8_t       g_h18[(size_t)BB * GHH];
__device__ unsigned char g_mask_u8[BB];

// scales: hidden x16, W x256, normed x64, weights x65536, values x16, cross(gatein) x16, h1 x64

// ---------------- helpers ----------------
__device__ __forceinline__ uint32_t smem_u32(const void* p) {
    return (uint32_t)__cvta_generic_to_shared(p);
}
__device__ __forceinline__ uint8_t f2e4m3(float v) {
    return (uint8_t)__nv_cvt_float_to_fp8(v, __NV_SATFINITE, __NV_E4M3);
}

// ---------------- fused mask detect + expand (single block) ----------------
__global__ void mask_fused_kernel(const unsigned char* m, unsigned char* out) {
    __shared__ int s_nonbin, s_off4, s_fbad, s_bfbad, s_code;
    if (threadIdx.x == 0) { s_nonbin = 0; s_off4 = 0; s_fbad = 0; s_bfbad = 0; }
    __syncthreads();
    int nonbin = 0, off4 = 0, fbad = 0, bfbad = 0;
    for (int j = threadIdx.x; j < 8192; j += 256) {
        unsigned char b = m[j];
        if (b > 1) nonbin++;
        if ((j & 3) != 0 && b != 0) off4++;
    }
    const uint32_t* u = (const uint32_t*)m;
    for (int i = threadIdx.x; i < 2048; i += 256) {
        uint32_t w = u[i];
        if (!(w == 0u || w == 0x3f800000u)) fbad++;
    }
    const uint16_t* h = (const uint16_t*)m;
    for (int i = threadIdx.x; i < 4096; i += 256) {
        uint16_t x = h[i];
        if (!(x == 0 || x == 0x3f80)) bfbad++;
    }
    atomicAdd(&s_nonbin, nonbin);
    atomicAdd(&s_off4, off4);
    atomicAdd(&s_fbad, fbad);
    atomicAdd(&s_bfbad, bfbad);
    __syncthreads();
    if (threadIdx.x == 0) {
        int code;
        if (s_nonbin == 0) code = (s_off4 > 0) ? 0 : 1;
        else if (s_fbad == 0) code = 2;
        else if (s_bfbad == 0) code = 3;
        else code = 1;
        s_code = code;
    }
    __syncthreads();
    int code = s_code;
    for (int i = threadIdx.x; i < BB; i += 256) {
        bool v;
        if (code == 0)      v = ((const unsigned char*)m)[i] != 0;
        else if (code == 1) v = ((const int*)m)[i] != 0;
        else if (code == 2) v = ((const float*)m)[i] != 0.0f;
        else                v = (((const uint16_t*)m)[i] & 0x7fff) != 0;
        out[i] = v ? 1 : 0;
    }
}

// ---------------- fp32 -> fp8 convert (scale) ----------------
__global__ void f32_to_fp8_kernel(const float* __restrict__ in,
                                  uint8_t* __restrict__ out, float scale, long n4) {
    long i = (long)blockIdx.x * blockDim.x + threadIdx.x;
    if (i < n4) {
        float4 v = ((const float4*)in)[i];
        uint32_t p = (uint32_t)f2e4m3(v.x * scale) |
                     ((uint32_t)f2e4m3(v.y * scale) << 8) |
                     ((uint32_t)f2e4m3(v.z * scale) << 16) |
                     ((uint32_t)f2e4m3(v.w * scale) << 24);
        ((uint32_t*)out)[i] = p;
    }
}

// hidden -> g_hidden8 AND first half of g_gatein8, scale 16
__global__ void hidden_to_fp8_kernel(const float* __restrict__ in,
                                     uint8_t* __restrict__ out,
                                     uint8_t* __restrict__ gatein) {
    long i = ((long)blockIdx.x * blockDim.x + threadIdx.x);
    if (i >= (long)BB * HH / 4) return;
    float4 v = ((const float4*)in)[i];
    uint32_t p = (uint32_t)f2e4m3(v.x * 16.f) |
                 ((uint32_t)f2e4m3(v.y * 16.f) << 8) |
                 ((uint32_t)f2e4m3(v.z * 16.f) << 16) |
                 ((uint32_t)f2e4m3(v.w * 16.f) << 24);
    ((uint32_t*)out)[i] = p;
    long e = i * 4;
    long b = e >> 12;            // /HH
    int  j = (int)(e & (HH - 1));
    *(uint32_t*)(gatein + b * (2 * HH) + j) = p;
}

// ---------------- row L2 normalize: bf16 proj -> fp8 normed (x64) ----------------
__global__ void normalize_rows_kernel(const __nv_bfloat16* __restrict__ p,
                                      uint8_t* __restrict__ normed) {
    int row = blockIdx.x;
    const __nv_bfloat16* r = p + (size_t)row * HH;
    float s = 0.f;
    for (int j = threadIdx.x; j < HH; j += 256) {
        float v = __bfloat162float(r[j]);
        s += v * v;
    }
#pragma unroll
    for (int o = 16; o > 0; o >>= 1) s += __shfl_xor_sync(0xffffffffu, s, o);
    __shared__ float ws[8];
    int w = threadIdx.x >> 5, l = threadIdx.x & 31;
    if (l == 0) ws[w] = s;
    __syncthreads();
    if (threadIdx.x < 32) {
        float x = (threadIdx.x < 8) ? ws[threadIdx.x] : 0.f;
#pragma unroll
        for (int o = 4; o > 0; o >>= 1) x += __shfl_xor_sync(0xffffffffu, x, o);
        if (threadIdx.x == 0) ws[0] = x;
    }
    __syncthreads();
    float scale = 64.f / fmaxf(sqrtf(ws[0]), 1e-12f);
    uint8_t* nr = normed + (size_t)row * HH;
    for (int j = threadIdx.x; j < HH / 4; j += 256) {
        float v0 = __bfloat162float(r[j * 4 + 0]) * scale;
        float v1 = __bfloat162float(r[j * 4 + 1]) * scale;
        float v2 = __bfloat162float(r[j * 4 + 2]) * scale;
        float v3 = __bfloat162float(r[j * 4 + 3]) * scale;
        ((uint32_t*)nr)[j] = (uint32_t)f2e4m3(v0) | ((uint32_t)f2e4m3(v1) << 8) |
                             ((uint32_t)f2e4m3(v2) << 16) | ((uint32_t)f2e4m3(v3) << 24);
    }
}

// ---------------- masked softmax: f32 sim -> fp8 weights (x65536) ----------------
__global__ void softmax_mask_kernel(const float* __restrict__ sim,
                                    const unsigned char* __restrict__ mask,
                                    uint8_t* __restrict__ wts) {
    int row = blockIdx.x;
    __shared__ float sv[BB];
    __shared__ float red[8];
    const float* sr = sim + (size_t)row * BB;
    float mx = -INFINITY;
    for (int j = threadIdx.x; j < BB; j += 256) {
        float v = sr[j];
        if (j == row || mask[j] == 0) v = -INFINITY;
        sv[j] = v;
        mx = fmaxf(mx, v);
    }
#pragma unroll
    for (int o = 16; o > 0; o >>= 1) mx = fmaxf(mx, __shfl_xor_sync(0xffffffffu, mx, o));
    int w = threadIdx.x >> 5, l = threadIdx.x & 31;
    if (l == 0) red[w] = mx;
    __syncthreads();
    if (threadIdx.x < 32) {
        float x = (threadIdx.x < 8) ? red[threadIdx.x] : -INFINITY;
#pragma unroll
        for (int o = 4; o > 0; o >>= 1) x = fmaxf(x, __shfl_xor_sync(0xffffffffu, x, o));
        if (threadIdx.x == 0) red[0] = x;
    }
    __syncthreads();
    float M = red[0];
    __syncthreads();
    float sum = 0.f;
    for (int j = threadIdx.x; j < BB; j += 256) {
        float v = sv[j];
        float e = (v == -INFINITY) ? 0.f : __expf(v - M);
        sv[j] = e;
        sum += e;
    }
#pragma unroll
    for (int o = 16; o > 0; o >>= 1) sum += __shfl_xor_sync(0xffffffffu, sum, o);
    if (l == 0) red[w] = sum;
    __syncthreads();
    if (threadIdx.x < 32) {
        float x = (threadIdx.x < 8) ? red[threadIdx.x] : 0.f;
#pragma unroll
        for (int o = 4; o > 0; o >>= 1) x += __shfl_xor_sync(0xffffffffu, x, o);
        if (threadIdx.x == 0) red[0] = x;
    }
    __syncthreads();
    float S = red[0];
    float inv = (S > 0.f) ? 65536.f / S : 0.f;
    uint8_t* wr = wts + (size_t)row * BB;
    for (int j = threadIdx.x; j < BB / 4; j += 256) {
        ((uint32_t*)wr)[j] = (uint32_t)f2e4m3(sv[j * 4 + 0] * inv) |
                             ((uint32_t)f2e4m3(sv[j * 4 + 1] * inv) << 8) |
                             ((uint32_t)f2e4m3(sv[j * 4 + 2] * inv) << 16) |
                             ((uint32_t)f2e4m3(sv[j * 4 + 3] * inv) << 24);
    }
}

// ---------------- u8 transpose (values -> valuesT) ----------------
__global__ void transpose_u8_kernel(const uint8_t* __restrict__ in,
                                    uint8_t* __restrict__ out, int R, int C) {
    __shared__ uint8_t tile[32][33];
    int x = blockIdx.x * 32 + threadIdx.x;
    int y0 = blockIdx.y * 32 + threadIdx.y;
#pragma unroll
    for (int i = 0; i < 32; i += 8)
        tile[threadIdx.y + i][threadIdx.x] = in[(size_t)(y0 + i) * C + x];
    __syncthreads();
    int x2 = blockIdx.y * 32 + threadIdx.x;
    int y2 = blockIdx.x * 32 + threadIdx.y;
#pragma unroll
    for (int i = 0; i < 32; i += 8)
        out[(size_t)(y2 + i) * R + x2] = tile[threadIdx.x][threadIdx.y + i];
}

// ================= fp8 NT GEMM (mma.sync m16n8k32 e4m3): C = A * B^T =========
// CTA tile 128x128, warp tile 64x32 (8 warps 2Mx4N), K-stage 128 elements,
// 3-stage cp.async pipeline, 110.8KB smem -> 2 CTAs/SM (16 warps, 4/SMSP).
// EPI: 0=f32(desc), 1=bf16(desc), 2=fp8(desc*oscale),
//      3=cross: bf16 + fp8 into gatein second half,
//      4=gelu(desc*acc+bias)->fp8, 5=hid+sigmoid(desc*acc+bias)*cross->f32
#define SROWB 144
#define A_BYTES (128 * SROWB)
#define B_BYTES (128 * SROWB)
#define STAGE_BYTES (A_BYTES + B_BYTES)       // 36864
#define GEMM_DYN_SMEM (3 * STAGE_BYTES + 256) // 110848

template <int EPI>
__global__ void __launch_bounds__(256, 2)
gemm_nt_fp8(const uint8_t* __restrict__ A,
            const uint8_t* __restrict__ Bm,
            void* __restrict__ Cv,
            int M, int N, int K,
            float desc, float oscale,
            const float* __restrict__ bias,
            const float* __restrict__ hid,
            const __nv_bfloat16* __restrict__ crossp,
            uint8_t* __restrict__ out2) {
    extern __shared__ char dynsm[];
    const uint32_t sbase = (smem_u32(dynsm) + 127u) & ~127u;

    const int t = threadIdx.x;
    const int warp = t >> 5, lane = t & 31;
    const int wm = (warp & 1) * 64;
    const int wn = (warp >> 1) * 32;
    const int m0 = blockIdx.y * 128;
    const int n0 = blockIdx.x * 128;
    const int KT = K >> 7;                 // 128-element K stages

    float acc[4][4][4];
#pragma unroll
    for (int i = 0; i < 4; i++)
#pragma unroll
        for (int j = 0; j < 4; j++)
#pragma unroll
            for (int r = 0; r < 4; r++) acc[i][j][r] = 0.f;

    auto fill = [&](int kt, int st) {
        const uint32_t stb = sbase + st * STAGE_BYTES;
        const uint8_t* Ak = A + (size_t)m0 * K + (size_t)kt * 128;
        const uint8_t* Bk = Bm + (size_t)n0 * K + (size_t)kt * 128;
#pragma unroll
        for (int i = 0; i < 4; i++) {              // A: 128 rows x 128B
            int q = t + i * 256;
            int row = q >> 3, ch = q & 7;
            uint32_t dst = stb + row * SROWB + ch * 16;
            const void* gp = Ak + (size_t)row * K + ch * 16;
            asm volatile("cp.async.cg.shared.global [%0], [%1], 16;\n" ::"r"(dst), "l"(gp));
        }
#pragma unroll
        for (int i = 0; i < 4; i++) {              // B: 128 rows x 128B
            int q = t + i * 256;
            int row = q >> 3, ch = q & 7;
            uint32_t dst = stb + A_BYTES + row * SROWB + ch * 16;
            const void* gp = Bk + (size_t)row * K + ch * 16;
            asm volatile("cp.async.cg.shared.global [%0], [%1], 16;\n" ::"r"(dst), "l"(gp));
        }
    };

    fill(0, 0);
    asm volatile("cp.async.commit_group;\n" ::);
    if (KT > 1) fill(1, 1);
    asm volatile("cp.async.commit_group;\n" ::);

    for (int kt = 0; kt < KT; ++kt) {
        const int nf = kt + 2;
        if (nf < KT) fill(nf, nf % 3);
        asm volatile("cp.async.commit_group;\n" ::);
        asm volatile("cp.async.wait_group 2;\n" ::);
        __syncthreads();

        const uint32_t stb = sbase + (kt % 3) * STAGE_BYTES;
        const uint32_t aB = stb;
        const uint32_t bB = stb + A_BYTES;
#pragma unroll
        for (int ks = 0; ks < 4; ++ks) {           // k32 steps within 128-elem stage
            uint32_t af[4][4], bf[2][4];
#pragma unroll
            for (int i = 0; i < 4; i++) {
                uint32_t addr = aB + (uint32_t)((wm + i * 16 + (lane & 15)) * SROWB +
                                                ks * 32 + (lane >> 4) * 16);
                asm volatile("ldmatrix.sync.aligned.m8n8.x4.shared.b16 {%0,%1,%2,%3}, [%4];\n"
                             : "=r"(af[i][0]), "=r"(af[i][1]), "=r"(af[i][2]), "=r"(af[i][3])
                             : "r"(addr));
            }
#pragma unroll
            for (int jj = 0; jj < 2; jj++) {
                uint32_t addr = bB + (uint32_t)((wn + jj * 16 + (lane & 15)) * SROWB +
                                                ks * 32 + (lane >> 4) * 16);
                asm volatile("ldmatrix.sync.aligned.m8n8.x4.shared.b16 {%0,%1,%2,%3}, [%4];\n"
                             : "=r"(bf[jj][0]), "=r"(bf[jj][1]), "=r"(bf[jj][2]), "=r"(bf[jj][3])
                             : "r"(addr));
            }
#pragma unroll
            for (int i = 0; i < 4; i++) {
#pragma unroll
                for (int j = 0; j < 4; j++) {
                    const int jj = j >> 1, s = j & 1;
                    asm volatile(
                        "mma.sync.aligned.m16n8k32.row.col.f32.e4m3.e4m3.f32 "
                        "{%0,%1,%2,%3}, {%4,%5,%6,%7}, {%8,%9}, {%0,%1,%2,%3};\n"
                        : "+f"(acc[i][j][0]), "+f"(acc[i][j][1]),
                          "+f"(acc[i][j][2]), "+f"(acc[i][j][3])
                        : "r"(af[i][0]), "r"(af[i][1]), "r"(af[i][2]), "r"(af[i][3]),
                          "r"(bf[jj][s]), "r"(bf[jj][s + 2]));
                }
            }
        }
        __syncthreads();
    }

    // ----- epilogue -----
#pragma unroll
    for (int i = 0; i < 4; i++) {
        int row0 = m0 + wm + i * 16 + (lane >> 2);
#pragma unroll
        for (int j = 0; j < 4; j++) {
            int col = n0 + wn + j * 8 + (lane & 3) * 2;
#pragma unroll
            for (int h = 0; h < 2; h++) {
                int r = row0 + h * 8;
                float v0 = acc[i][j][h * 2 + 0] * desc;
                float v1 = acc[i][j][h * 2 + 1] * desc;
                size_t off = (size_t)r * N + col;
                if (EPI == 0) {
                    *(float2*)((float*)Cv + off) = make_float2(v0, v1);
                } else if (EPI == 1) {
                    *(__nv_bfloat162*)((__nv_bfloat16*)Cv + off) =
                        __floats2bfloat162_rn(v0, v1);
                } else if (EPI == 2) {
                    uint16_t p = (uint16_t)f2e4m3(v0 * oscale) |
                                 ((uint16_t)f2e4m3(v1 * oscale) << 8);
                    *(uint16_t*)((uint8_t*)Cv + off) = p;
                } else if (EPI == 3) {
                    *(__nv_bfloat162*)((__nv_bfloat16*)Cv + off) =
                        __floats2bfloat162_rn(v0, v1);
                    uint16_t p = (uint16_t)f2e4m3(v0 * oscale) |
                                 ((uint16_t)f2e4m3(v1 * oscale) << 8);
                    *(uint16_t*)(out2 + (size_t)r * (2 * HH) + HH + col) = p;
                } else if (EPI == 4) {
                    float x0 = v0 + bias[col], x1 = v1 + bias[col + 1];
                    float g0 = 0.5f * x0 * (1.f + erff(x0 * 0.70710678118654752f));
                    float g1 = 0.5f * x1 * (1.f + erff(x1 * 0.70710678118654752f));
                    uint16_t p = (uint16_t)f2e4m3(g0 * oscale) |
                                 ((uint16_t)f2e4m3(g1 * oscale) << 8);
                    *(uint16_t*)((uint8_t*)Cv + off) = p;
                } else {
                    float x0 = v0 + bias[col], x1 = v1 + bias[col + 1];
                    float s0 = 1.f / (1.f + expf(-x0));
                    float s1 = 1.f / (1.f + expf(-x1));
                    __nv_bfloat162 cc = *(const __nv_bfloat162*)(crossp + off);
                    float2 hv = *(const float2*)(hid + off);
                    *(float2*)((float*)Cv + off) =
                        make_float2(hv.x + s0 * __bfloat162float(cc.x),
                                    hv.y + s1 * __bfloat162float(cc.y));
                }
            }
        }
    }
}

// ---------------- host launcher ----------------
extern "C" void kernel_launch(void* const* d_in, const int* in_sizes, int n_in,
                              void* d_out, int out_size) {
    (void)in_sizes; (void)n_in; (void)out_size;
    const float* hidden = (const float*)d_in[0];
    const void*  amask  = d_in[1];
    const float* Wsim   = (const float*)d_in[2];
    const float* Wval   = (const float*)d_in[3];
    const float* Wg1    = (const float*)d_in[4];
    const float* bg1    = (const float*)d_in[5];
    const float* Wg2    = (const float*)d_in[6];
    const float* bg2    = (const float*)d_in[7];
    float* out = (float*)d_out;

    uint8_t *h8, *wsim8, *wval8, *wg18, *wg28, *normed8, *vals8, *valsT8, *wts8, *gin8, *h18;
    __nv_bfloat16 *proj, *cross;
    float* sim;
    unsigned char* mask;
    cudaGetSymbolAddress((void**)&h8,      g_hidden8);
    cudaGetSymbolAddress((void**)&wsim8,   g_Wsim8);
    cudaGetSymbolAddress((void**)&wval8,   g_Wval8);
    cudaGetSymbolAddress((void**)&wg18,    g_Wg18);
    cudaGetSymbolAddress((void**)&wg28,    g_Wg28);
    cudaGetSymbolAddress((void**)&proj,    g_proj_bf);
    cudaGetSymbolAddress((void**)&normed8, g_normed8);
    cudaGetSymbolAddress((void**)&vals8,   g_values8);
    cudaGetSymbolAddress((void**)&valsT8,  g_valuesT8);
    cudaGetSymbolAddress((void**)&sim,     g_sim_f32);
    cudaGetSymbolAddress((void**)&wts8,    g_weights8);
    cudaGetSymbolAddress((void**)&cross,   g_cross_bf);
    cudaGetSymbolAddress((void**)&gin8,    g_gatein8);
    cudaGetSymbolAddress((void**)&h18,     g_h18);
    cudaGetSymbolAddress((void**)&mask,    g_mask_u8);

    cudaFuncSetAttribute(gemm_nt_fp8<0>, cudaFuncAttributeMaxDynamicSharedMemorySize, GEMM_DYN_SMEM);
    cudaFuncSetAttribute(gemm_nt_fp8<1>, cudaFuncAttributeMaxDynamicSharedMemorySize, GEMM_DYN_SMEM);
    cudaFuncSetAttribute(gemm_nt_fp8<2>, cudaFuncAttributeMaxDynamicSharedMemorySize, GEMM_DYN_SMEM);
    cudaFuncSetAttribute(gemm_nt_fp8<3>, cudaFuncAttributeMaxDynamicSharedMemorySize, GEMM_DYN_SMEM);
    cudaFuncSetAttribute(gemm_nt_fp8<4>, cudaFuncAttributeMaxDynamicSharedMemorySize, GEMM_DYN_SMEM);
    cudaFuncSetAttribute(gemm_nt_fp8<5>, cudaFuncAttributeMaxDynamicSharedMemorySize, GEMM_DYN_SMEM);

    // Launch order matters: ncu -s 5 -c 1 captures launch index 5 == sim GEMM.
    // 0: fused mask
    mask_fused_kernel<<<1, 256>>>((const unsigned char*)amask, mask);
    // 1: hidden -> fp8 (x16) + gatein first half
    hidden_to_fp8_kernel<<<(unsigned)(((long)BB * HH / 4 + 255) / 256), 256>>>(hidden, h8, gin8);
    // 2: Wsim -> fp8 (x256)
    {
        long n4 = (long)HH * HH / 4;
        f32_to_fp8_kernel<<<(unsigned)((n4 + 255) / 256), 256>>>(Wsim, wsim8, 256.f, n4);
    }
    // 3: proj = hidden @ Wsim^T -> bf16   (desc 1/(16*256))
    gemm_nt_fp8<1><<<dim3(HH / 128, BB / 128), 256, GEMM_DYN_SMEM>>>(
        h8, wsim8, proj, BB, HH, HH, 1.f / 4096.f, 0.f, nullptr, nullptr, nullptr, nullptr);
    // 4: normalize -> normed fp8 (x64)
    normalize_rows_kernel<<<BB, 256>>>(proj, normed8);
    // 5: sim = normed @ normed^T -> f32   (desc 1/(64*64))   [ncu capture target]
    gemm_nt_fp8<0><<<dim3(BB / 128, BB / 128), 256, GEMM_DYN_SMEM>>>(
        normed8, normed8, sim, BB, BB, HH, 1.f / 4096.f, 0.f, nullptr, nullptr, nullptr, nullptr);
    // 6: Wval -> fp8 (x256)
    {
        long n4 = (long)HH * HH / 4;
        f32_to_fp8_kernel<<<(unsigned)((n4 + 255) / 256), 256>>>(Wval, wval8, 256.f, n4);
    }
    // 7: softmax -> weights fp8 (x65536)
    softmax_mask_kernel<<<BB, 256>>>(sim, mask, wts8);
    // 8: values = hidden @ Wval^T -> fp8 (x16)
    gemm_nt_fp8<2><<<dim3(HH / 128, BB / 128), 256, GEMM_DYN_SMEM>>>(
        h8, wval8, vals8, BB, HH, HH, 1.f / 4096.f, 16.f, nullptr, nullptr, nullptr, nullptr);
    // 9: transpose values -> valuesT
    transpose_u8_kernel<<<dim3(HH / 32, BB / 32), dim3(32, 8)>>>(vals8, valsT8, BB, HH);
    // 10: cross = weights @ values -> bf16 + fp8(x16) into gatein[:, H:2H]
    gemm_nt_fp8<3><<<dim3(HH / 128, BB / 128), 256, GEMM_DYN_SMEM>>>(
        wts8, valsT8, cross, BB, HH, BB, 1.f / 1048576.f, 16.f, nullptr, nullptr, nullptr, gin8);
    // 11: Wg1 -> fp8 (x256)
    {
        long n4 = (long)GHH * 2 * HH / 4;
        f32_to_fp8_kernel<<<(unsigned)((n4 + 255) / 256), 256>>>(Wg1, wg18, 256.f, n4);
    }
    // 12: h1 = gelu(gatein @ Wg1^T + b1) -> fp8 (x64)   (desc 1/(16*256))
    gemm_nt_fp8<4><<<dim3(GHH / 128, BB / 128), 256, GEMM_DYN_SMEM>>>(
        gin8, wg18, h18, BB, GHH, 2 * HH, 1.f / 4096.f, 64.f, bg1, nullptr, nullptr, nullptr);
    // 13: Wg2 -> fp8 (x256)
    {
        long n4 = (long)HH * GHH / 4;
        f32_to_fp8_kernel<<<(unsigned)((n4 + 255) / 256), 256>>>(Wg2, wg28, 256.f, n4);
    }
    // 14: out = hidden + sigmoid(h1 @ Wg2^T + b2) * cross   (desc 1/(64*256))
    gemm_nt_fp8<5><<<dim3(HH / 128, BB / 128), 256, GEMM_DYN_SMEM>>>(
        h18, wg28, out, BB, HH, GHH, 1.f / 16384.f, 0.f, bg2, hidden, cross, nullptr);
}

// round 7
// speedup vs baseline: 1.3477x; 1.1617x over previous
#include <cuda_runtime.h>
#include <cuda_bf16.h>
#include <cuda_fp8.h>
#include <cstdint>
#include <math.h>

#define BB 8192
#define HH 4096
#define GHH 1024

// ---------------- scratch (device globals; allocation-free rule) ----------------
__device__ uint8_t       g_hidden8[(size_t)BB * HH];
__device__ uint8_t       g_Wsim8[(size_t)HH * HH];
__device__ uint8_t       g_Wval8[(size_t)HH * HH];
__device__ uint8_t       g_Wg18[(size_t)GHH * 2 * HH];
__device__ uint8_t       g_Wg28[(size_t)HH * GHH];
__device__ __nv_bfloat16 g_proj_bf[(size_t)BB * HH];
__device__ uint8_t       g_normed8[(size_t)BB * HH];
__device__ uint8_t       g_values8[(size_t)BB * HH];
__device__ uint8_t       g_valuesT8[(size_t)HH * BB];
__device__ float         g_sim_f32[(size_t)BB * BB];
__device__ uint8_t       g_weights8[(size_t)BB * BB];
__device__ __nv_bfloat16 g_cross_bf[(size_t)BB * HH];
__device__ uint8_t       g_gatein8[(size_t)BB * 2 * HH];
__device__ uint8_t       g_h18[(size_t)BB * GHH];
__device__ unsigned char g_mask_u8[BB];

// scales: hidden x16, W x256, normed x64, weights x65536, values x16, cross(gatein) x16, h1 x64

// ---------------- helpers ----------------
__device__ __forceinline__ uint32_t smem_u32(const void* p) {
    return (uint32_t)__cvta_generic_to_shared(p);
}
__device__ __forceinline__ uint8_t f2e4m3(float v) {
    return (uint8_t)__nv_cvt_float_to_fp8(v, __NV_SATFINITE, __NV_E4M3);
}

// ---------------- fused mask detect + expand (single block) ----------------
__global__ void mask_fused_kernel(const unsigned char* m, unsigned char* out) {
    __shared__ int s_nonbin, s_off4, s_fbad, s_bfbad, s_code;
    if (threadIdx.x == 0) { s_nonbin = 0; s_off4 = 0; s_fbad = 0; s_bfbad = 0; }
    __syncthreads();
    int nonbin = 0, off4 = 0, fbad = 0, bfbad = 0;
    for (int j = threadIdx.x; j < 8192; j += 256) {
        unsigned char b = m[j];
        if (b > 1) nonbin++;
        if ((j & 3) != 0 && b != 0) off4++;
    }
    const uint32_t* u = (const uint32_t*)m;
    for (int i = threadIdx.x; i < 2048; i += 256) {
        uint32_t w = u[i];
        if (!(w == 0u || w == 0x3f800000u)) fbad++;
    }
    const uint16_t* h = (const uint16_t*)m;
    for (int i = threadIdx.x; i < 4096; i += 256) {
        uint16_t x = h[i];
        if (!(x == 0 || x == 0x3f80)) bfbad++;
    }
    atomicAdd(&s_nonbin, nonbin);
    atomicAdd(&s_off4, off4);
    atomicAdd(&s_fbad, fbad);
    atomicAdd(&s_bfbad, bfbad);
    __syncthreads();
    if (threadIdx.x == 0) {
        int code;
        if (s_nonbin == 0) code = (s_off4 > 0) ? 0 : 1;
        else if (s_fbad == 0) code = 2;
        else if (s_bfbad == 0) code = 3;
        else code = 1;
        s_code = code;
    }
    __syncthreads();
    int code = s_code;
    for (int i = threadIdx.x; i < BB; i += 256) {
        bool v;
        if (code == 0)      v = ((const unsigned char*)m)[i] != 0;
        else if (code == 1) v = ((const int*)m)[i] != 0;
        else if (code == 2) v = ((const float*)m)[i] != 0.0f;
        else                v = (((const uint16_t*)m)[i] & 0x7fff) != 0;
        out[i] = v ? 1 : 0;
    }
}

// ---------------- fp32 -> fp8 convert (scale) ----------------
__global__ void f32_to_fp8_kernel(const float* __restrict__ in,
                                  uint8_t* __restrict__ out, float scale, long n4) {
    long i = (long)blockIdx.x * blockDim.x + threadIdx.x;
    if (i < n4) {
        float4 v = ((const float4*)in)[i];
        uint32_t p = (uint32_t)f2e4m3(v.x * scale) |
                     ((uint32_t)f2e4m3(v.y * scale) << 8) |
                     ((uint32_t)f2e4m3(v.z * scale) << 16) |
                     ((uint32_t)f2e4m3(v.w * scale) << 24);
        ((uint32_t*)out)[i] = p;
    }
}

// hidden -> g_hidden8 AND first half of g_gatein8, scale 16
__global__ void hidden_to_fp8_kernel(const float* __restrict__ in,
                                     uint8_t* __restrict__ out,
                                     uint8_t* __restrict__ gatein) {
    long i = ((long)blockIdx.x * blockDim.x + threadIdx.x);
    if (i >= (long)BB * HH / 4) return;
    float4 v = ((const float4*)in)[i];
    uint32_t p = (uint32_t)f2e4m3(v.x * 16.f) |
                 ((uint32_t)f2e4m3(v.y * 16.f) << 8) |
                 ((uint32_t)f2e4m3(v.z * 16.f) << 16) |
                 ((uint32_t)f2e4m3(v.w * 16.f) << 24);
    ((uint32_t*)out)[i] = p;
    long e = i * 4;
    long b = e >> 12;            // /HH
    int  j = (int)(e & (HH - 1));
    *(uint32_t*)(gatein + b * (2 * HH) + j) = p;
}

// ---------------- row L2 normalize: bf16 proj -> fp8 normed (x64) ----------------
__global__ void normalize_rows_kernel(const __nv_bfloat16* __restrict__ p,
                                      uint8_t* __restrict__ normed) {
    int row = blockIdx.x;
    const __nv_bfloat16* r = p + (size_t)row * HH;
    float s = 0.f;
    for (int j = threadIdx.x; j < HH; j += 256) {
        float v = __bfloat162float(r[j]);
        s += v * v;
    }
#pragma unroll
    for (int o = 16; o > 0; o >>= 1) s += __shfl_xor_sync(0xffffffffu, s, o);
    __shared__ float ws[8];
    int w = threadIdx.x >> 5, l = threadIdx.x & 31;
    if (l == 0) ws[w] = s;
    __syncthreads();
    if (threadIdx.x < 32) {
        float x = (threadIdx.x < 8) ? ws[threadIdx.x] : 0.f;
#pragma unroll
        for (int o = 4; o > 0; o >>= 1) x += __shfl_xor_sync(0xffffffffu, x, o);
        if (threadIdx.x == 0) ws[0] = x;
    }
    __syncthreads();
    float scale = 64.f / fmaxf(sqrtf(ws[0]), 1e-12f);
    uint8_t* nr = normed + (size_t)row * HH;
    for (int j = threadIdx.x; j < HH / 4; j += 256) {
        float v0 = __bfloat162float(r[j * 4 + 0]) * scale;
        float v1 = __bfloat162float(r[j * 4 + 1]) * scale;
        float v2 = __bfloat162float(r[j * 4 + 2]) * scale;
        float v3 = __bfloat162float(r[j * 4 + 3]) * scale;
        ((uint32_t*)nr)[j] = (uint32_t)f2e4m3(v0) | ((uint32_t)f2e4m3(v1) << 8) |
                             ((uint32_t)f2e4m3(v2) << 16) | ((uint32_t)f2e4m3(v3) << 24);
    }
}

// ---------------- masked softmax: f32 sim -> fp8 weights (x65536) ----------------
__global__ void softmax_mask_kernel(const float* __restrict__ sim,
                                    const unsigned char* __restrict__ mask,
                                    uint8_t* __restrict__ wts) {
    int row = blockIdx.x;
    __shared__ float sv[BB];
    __shared__ float red[8];
    const float* sr = sim + (size_t)row * BB;
    float mx = -INFINITY;
    for (int j = threadIdx.x; j < BB; j += 256) {
        float v = sr[j];
        if (j == row || mask[j] == 0) v = -INFINITY;
        sv[j] = v;
        mx = fmaxf(mx, v);
    }
#pragma unroll
    for (int o = 16; o > 0; o >>= 1) mx = fmaxf(mx, __shfl_xor_sync(0xffffffffu, mx, o));
    int w = threadIdx.x >> 5, l = threadIdx.x & 31;
    if (l == 0) red[w] = mx;
    __syncthreads();
    if (threadIdx.x < 32) {
        float x = (threadIdx.x < 8) ? red[threadIdx.x] : -INFINITY;
#pragma unroll
        for (int o = 4; o > 0; o >>= 1) x = fmaxf(x, __shfl_xor_sync(0xffffffffu, x, o));
        if (threadIdx.x == 0) red[0] = x;
    }
    __syncthreads();
    float M = red[0];
    __syncthreads();
    float sum = 0.f;
    for (int j = threadIdx.x; j < BB; j += 256) {
        float v = sv[j];
        float e = (v == -INFINITY) ? 0.f : __expf(v - M);
        sv[j] = e;
        sum += e;
    }
#pragma unroll
    for (int o = 16; o > 0; o >>= 1) sum += __shfl_xor_sync(0xffffffffu, sum, o);
    if (l == 0) red[w] = sum;
    __syncthreads();
    if (threadIdx.x < 32) {
        float x = (threadIdx.x < 8) ? red[threadIdx.x] : 0.f;
#pragma unroll
        for (int o = 4; o > 0; o >>= 1) x += __shfl_xor_sync(0xffffffffu, x, o);
        if (threadIdx.x == 0) red[0] = x;
    }
    __syncthreads();
    float S = red[0];
    float inv = (S > 0.f) ? 65536.f / S : 0.f;
    uint8_t* wr = wts + (size_t)row * BB;
    for (int j = threadIdx.x; j < BB / 4; j += 256) {
        ((uint32_t*)wr)[j] = (uint32_t)f2e4m3(sv[j * 4 + 0] * inv) |
                             ((uint32_t)f2e4m3(sv[j * 4 + 1] * inv) << 8) |
                             ((uint32_t)f2e4m3(sv[j * 4 + 2] * inv) << 16) |
                             ((uint32_t)f2e4m3(sv[j * 4 + 3] * inv) << 24);
    }
}

// ---------------- u8 transpose (values -> valuesT) ----------------
__global__ void transpose_u8_kernel(const uint8_t* __restrict__ in,
                                    uint8_t* __restrict__ out, int R, int C) {
    __shared__ uint8_t tile[32][33];
    int x = blockIdx.x * 32 + threadIdx.x;
    int y0 = blockIdx.y * 32 + threadIdx.y;
#pragma unroll
    for (int i = 0; i < 32; i += 8)
        tile[threadIdx.y + i][threadIdx.x] = in[(size_t)(y0 + i) * C + x];
    __syncthreads();
    int x2 = blockIdx.y * 32 + threadIdx.x;
    int y2 = blockIdx.x * 32 + threadIdx.y;
#pragma unroll
    for (int i = 0; i < 32; i += 8)
        out[(size_t)(y2 + i) * R + x2] = tile[threadIdx.x][threadIdx.y + i];
}

// ================= fp8 NT GEMM (mma.sync m16n8k32 e4m3): C = A * B^T =========
// CTA tile 128x128, warp tile 64x32 (8 warps 2Mx4N), K-stage 128 elements,
// 3-stage cp.async pipeline, 110.8KB smem -> 2 CTAs/SM.
// Address math hoisted: per-warp frag offsets precomputed, per-ldmatrix = 1 IADD.
// EPI: 0=f32(desc), 1=bf16(desc), 2=fp8(desc*oscale),
//      3=cross: bf16 + fp8 into gatein second half,
//      4=gelu(desc*acc+bias)->fp8, 5=hid+sigmoid(desc*acc+bias)*cross->f32,
//      6=f32(desc) symmetric: only bx<=by blocks run; writes C and C^T
#define SROWB 144
#define A_BYTES (128 * SROWB)
#define B_BYTES (128 * SROWB)
#define STAGE_BYTES (A_BYTES + B_BYTES)       // 36864
#define GEMM_DYN_SMEM (3 * STAGE_BYTES + 256) // 110848

template <int EPI>
__global__ void __launch_bounds__(256, 2)
gemm_nt_fp8(const uint8_t* __restrict__ A,
            const uint8_t* __restrict__ Bm,
            void* __restrict__ Cv,
            int M, int N, int K,
            float desc, float oscale,
            const float* __restrict__ bias,
            const float* __restrict__ hid,
            const __nv_bfloat16* __restrict__ crossp,
            uint8_t* __restrict__ out2) {
    if (EPI == 6 && blockIdx.x > blockIdx.y) return;   // symmetric: lower triangle only

    extern __shared__ char dynsm[];
    const uint32_t sbase = (smem_u32(dynsm) + 127u) & ~127u;

    const int t = threadIdx.x;
    const int warp = t >> 5, lane = t & 31;
    const int wm = (warp & 1) * 64;
    const int wn = (warp >> 1) * 32;
    const int m0 = blockIdx.y * 128;
    const int n0 = blockIdx.x * 128;
    const int KT = K >> 7;                 // 128-element K stages

    // ---- hoisted producer addressing (per thread) ----
    const int frow = t >> 3;               // 0..31
    const int fchb = (t & 7) * 16;         // byte offset in row
    const uint32_t sAoff = (uint32_t)frow * SROWB + fchb;                 // + i*32*SROWB
    const uint32_t sBoff = A_BYTES + (uint32_t)frow * SROWB + fchb;
    const uint8_t* gA = A + (size_t)(m0 + frow) * K + fchb;               // + i*32*K + kt*128
    const uint8_t* gB = Bm + (size_t)(n0 + frow) * K + fchb;

    // ---- hoisted consumer addressing (per lane) ----
    const uint32_t aOff0 = (uint32_t)(wm + (lane & 15)) * SROWB + (lane >> 4) * 16;
    const uint32_t bOff0 = A_BYTES + (uint32_t)(wn + (lane & 15)) * SROWB + (lane >> 4) * 16;

    float acc[4][4][4];
#pragma unroll
    for (int i = 0; i < 4; i++)
#pragma unroll
        for (int j = 0; j < 4; j++)
#pragma unroll
            for (int r = 0; r < 4; r++) acc[i][j][r] = 0.f;

    auto fill = [&](int kt, int st) {
        const uint32_t stb = sbase + st * STAGE_BYTES;
        const size_t kb = (size_t)kt * 128;
#pragma unroll
        for (int i = 0; i < 4; i++) {
            uint32_t dst = stb + sAoff + i * (32 * SROWB);
            const void* gp = gA + kb + (size_t)i * 32 * K;
            asm volatile("cp.async.cg.shared.global [%0], [%1], 16;\n" ::"r"(dst), "l"(gp));
        }
#pragma unroll
        for (int i = 0; i < 4; i++) {
            uint32_t dst = stb + sBoff + i * (32 * SROWB);
            const void* gp = gB + kb + (size_t)i * 32 * K;
            asm volatile("cp.async.cg.shared.global [%0], [%1], 16;\n" ::"r"(dst), "l"(gp));
        }
    };

    fill(0, 0);
    asm volatile("cp.async.commit_group;\n" ::);
    if (KT > 1) fill(1, 1);
    asm volatile("cp.async.commit_group;\n" ::);

    for (int kt = 0; kt < KT; ++kt) {
        const int nf = kt + 2;
        if (nf < KT) fill(nf, nf % 3);
        asm volatile("cp.async.commit_group;\n" ::);
        asm volatile("cp.async.wait_group 2;\n" ::);
        __syncthreads();

        const uint32_t stb = sbase + (kt % 3) * STAGE_BYTES;
        const uint32_t aBase = stb + aOff0;    // single add per stage
        const uint32_t bBase = stb + bOff0;
#pragma unroll
        for (int ks = 0; ks < 4; ++ks) {       // k32 steps; offsets are immediates
            uint32_t af[4][4], bf[2][4];
#pragma unroll
            for (int i = 0; i < 4; i++) {
                uint32_t addr = aBase + (uint32_t)(i * 16 * SROWB + ks * 32);
                asm volatile("ldmatrix.sync.aligned.m8n8.x4.shared.b16 {%0,%1,%2,%3}, [%4];\n"
                             : "=r"(af[i][0]), "=r"(af[i][1]), "=r"(af[i][2]), "=r"(af[i][3])
                             : "r"(addr));
            }
#pragma unroll
            for (int jj = 0; jj < 2; jj++) {
                uint32_t addr = bBase + (uint32_t)(jj * 16 * SROWB + ks * 32);
                asm volatile("ldmatrix.sync.aligned.m8n8.x4.shared.b16 {%0,%1,%2,%3}, [%4];\n"
                             : "=r"(bf[jj][0]), "=r"(bf[jj][1]), "=r"(bf[jj][2]), "=r"(bf[jj][3])
                             : "r"(addr));
            }
#pragma unroll
            for (int i = 0; i < 4; i++) {
#pragma unroll
                for (int j = 0; j < 4; j++) {
                    const int jj = j >> 1, s = j & 1;
                    asm volatile(
                        "mma.sync.aligned.m16n8k32.row.col.f32.e4m3.e4m3.f32 "
                        "{%0,%1,%2,%3}, {%4,%5,%6,%7}, {%8,%9}, {%0,%1,%2,%3};\n"
                        : "+f"(acc[i][j][0]), "+f"(acc[i][j][1]),
                          "+f"(acc[i][j][2]), "+f"(acc[i][j][3])
                        : "r"(af[i][0]), "r"(af[i][1]), "r"(af[i][2]), "r"(af[i][3]),
                          "r"(bf[jj][s]), "r"(bf[jj][s + 2]));
                }
            }
        }
        __syncthreads();
    }

    // ----- epilogue -----
#pragma unroll
    for (int i = 0; i < 4; i++) {
        int row0 = m0 + wm + i * 16 + (lane >> 2);
#pragma unroll
        for (int j = 0; j < 4; j++) {
            int col = n0 + wn + j * 8 + (lane & 3) * 2;
#pragma unroll
            for (int h = 0; h < 2; h++) {
                int r = row0 + h * 8;
                float v0 = acc[i][j][h * 2 + 0] * desc;
                float v1 = acc[i][j][h * 2 + 1] * desc;
                size_t off = (size_t)r * N + col;
                if (EPI == 0) {
                    *(float2*)((float*)Cv + off) = make_float2(v0, v1);
                } else if (EPI == 6) {
                    *(float2*)((float*)Cv + off) = make_float2(v0, v1);
                    if (blockIdx.x != blockIdx.y) {
                        ((float*)Cv)[(size_t)col * N + r] = v0;
                        ((float*)Cv)[(size_t)(col + 1) * N + r] = v1;
                    }
                } else if (EPI == 1) {
                    *(__nv_bfloat162*)((__nv_bfloat16*)Cv + off) =
                        __floats2bfloat162_rn(v0, v1);
                } else if (EPI == 2) {
                    uint16_t p = (uint16_t)f2e4m3(v0 * oscale) |
                                 ((uint16_t)f2e4m3(v1 * oscale) << 8);
                    *(uint16_t*)((uint8_t*)Cv + off) = p;
                } else if (EPI == 3) {
                    *(__nv_bfloat162*)((__nv_bfloat16*)Cv + off) =
                        __floats2bfloat162_rn(v0, v1);
                    uint16_t p = (uint16_t)f2e4m3(v0 * oscale) |
                                 ((uint16_t)f2e4m3(v1 * oscale) << 8);
                    *(uint16_t*)(out2 + (size_t)r * (2 * HH) + HH + col) = p;
                } else if (EPI == 4) {
                    float x0 = v0 + bias[col], x1 = v1 + bias[col + 1];
                    float g0 = 0.5f * x0 * (1.f + erff(x0 * 0.70710678118654752f));
                    float g1 = 0.5f * x1 * (1.f + erff(x1 * 0.70710678118654752f));
                    uint16_t p = (uint16_t)f2e4m3(g0 * oscale) |
                                 ((uint16_t)f2e4m3(g1 * oscale) << 8);
                    *(uint16_t*)((uint8_t*)Cv + off) = p;
                } else {
                    float x0 = v0 + bias[col], x1 = v1 + bias[col + 1];
                    float s0 = 1.f / (1.f + expf(-x0));
                    float s1 = 1.f / (1.f + expf(-x1));
                    __nv_bfloat162 cc = *(const __nv_bfloat162*)(crossp + off);
                    float2 hv = *(const float2*)(hid + off);
                    *(float2*)((float*)Cv + off) =
                        make_float2(hv.x + s0 * __bfloat162float(cc.x),
                                    hv.y + s1 * __bfloat162float(cc.y));
                }
            }
        }
    }
}

// ---------------- host launcher ----------------
extern "C" void kernel_launch(void* const* d_in, const int* in_sizes, int n_in,
                              void* d_out, int out_size) {
    (void)in_sizes; (void)n_in; (void)out_size;
    const float* hidden = (const float*)d_in[0];
    const void*  amask  = d_in[1];
    const float* Wsim   = (const float*)d_in[2];
    const float* Wval   = (const float*)d_in[3];
    const float* Wg1    = (const float*)d_in[4];
    const float* bg1    = (const float*)d_in[5];
    const float* Wg2    = (const float*)d_in[6];
    const float* bg2    = (const float*)d_in[7];
    float* out = (float*)d_out;

    uint8_t *h8, *wsim8, *wval8, *wg18, *wg28, *normed8, *vals8, *valsT8, *wts8, *gin8, *h18;
    __nv_bfloat16 *proj, *cross;
    float* sim;
    unsigned char* mask;
    cudaGetSymbolAddress((void**)&h8,      g_hidden8);
    cudaGetSymbolAddress((void**)&wsim8,   g_Wsim8);
    cudaGetSymbolAddress((void**)&wval8,   g_Wval8);
    cudaGetSymbolAddress((void**)&wg18,    g_Wg18);
    cudaGetSymbolAddress((void**)&wg28,    g_Wg28);
    cudaGetSymbolAddress((void**)&proj,    g_proj_bf);
    cudaGetSymbolAddress((void**)&normed8, g_normed8);
    cudaGetSymbolAddress((void**)&vals8,   g_values8);
    cudaGetSymbolAddress((void**)&valsT8,  g_valuesT8);
    cudaGetSymbolAddress((void**)&sim,     g_sim_f32);
    cudaGetSymbolAddress((void**)&wts8,    g_weights8);
    cudaGetSymbolAddress((void**)&cross,   g_cross_bf);
    cudaGetSymbolAddress((void**)&gin8,    g_gatein8);
    cudaGetSymbolAddress((void**)&h18,     g_h18);
    cudaGetSymbolAddress((void**)&mask,    g_mask_u8);

    cudaFuncSetAttribute(gemm_nt_fp8<0>, cudaFuncAttributeMaxDynamicSharedMemorySize, GEMM_DYN_SMEM);
    cudaFuncSetAttribute(gemm_nt_fp8<1>, cudaFuncAttributeMaxDynamicSharedMemorySize, GEMM_DYN_SMEM);
    cudaFuncSetAttribute(gemm_nt_fp8<2>, cudaFuncAttributeMaxDynamicSharedMemorySize, GEMM_DYN_SMEM);
    cudaFuncSetAttribute(gemm_nt_fp8<3>, cudaFuncAttributeMaxDynamicSharedMemorySize, GEMM_DYN_SMEM);
    cudaFuncSetAttribute(gemm_nt_fp8<4>, cudaFuncAttributeMaxDynamicSharedMemorySize, GEMM_DYN_SMEM);
    cudaFuncSetAttribute(gemm_nt_fp8<5>, cudaFuncAttributeMaxDynamicSharedMemorySize, GEMM_DYN_SMEM);
    cudaFuncSetAttribute(gemm_nt_fp8<6>, cudaFuncAttributeMaxDynamicSharedMemorySize, GEMM_DYN_SMEM);

    // Launch order: ncu -s 5 -c 1 captures index 5 == sim GEMM (symmetric).
    // 0: fused mask
    mask_fused_kernel<<<1, 256>>>((const unsigned char*)amask, mask);
    // 1: hidden -> fp8 (x16) + gatein first half
    hidden_to_fp8_kernel<<<(unsigned)(((long)BB * HH / 4 + 255) / 256), 256>>>(hidden, h8, gin8);
    // 2: Wsim -> fp8 (x256)
    {
        long n4 = (long)HH * HH / 4;
        f32_to_fp8_kernel<<<(unsigned)((n4 + 255) / 256), 256>>>(Wsim, wsim8, 256.f, n4);
    }
    // 3: proj = hidden @ Wsim^T -> bf16   (desc 1/(16*256))
    gemm_nt_fp8<1><<<dim3(HH / 128, BB / 128), 256, GEMM_DYN_SMEM>>>(
        h8, wsim8, proj, BB, HH, HH, 1.f / 4096.f, 0.f, nullptr, nullptr, nullptr, nullptr);
    // 4: normalize -> normed fp8 (x64)
    normalize_rows_kernel<<<BB, 256>>>(proj, normed8);
    // 5: sim = normed @ normed^T -> f32, symmetric (desc 1/(64*64))  [ncu target]
    gemm_nt_fp8<6><<<dim3(BB / 128, BB / 128), 256, GEMM_DYN_SMEM>>>(
        normed8, normed8, sim, BB, BB, HH, 1.f / 4096.f, 0.f, nullptr, nullptr, nullptr, nullptr);
    // 6: Wval -> fp8 (x256)
    {
        long n4 = (long)HH * HH / 4;
        f32_to_fp8_kernel<<<(unsigned)((n4 + 255) / 256), 256>>>(Wval, wval8, 256.f, n4);
    }
    // 7: softmax -> weights fp8 (x65536)
    softmax_mask_kernel<<<BB, 256>>>(sim, mask, wts8);
    // 8: values = hidden @ Wval^T -> fp8 (x16)
    gemm_nt_fp8<2><<<dim3(HH / 128, BB / 128), 256, GEMM_DYN_SMEM>>>(
        h8, wval8, vals8, BB, HH, HH, 1.f / 4096.f, 16.f, nullptr, nullptr, nullptr, nullptr);
    // 9: transpose values -> valuesT
    transpose_u8_kernel<<<dim3(HH / 32, BB / 32), dim3(32, 8)>>>(vals8, valsT8, BB, HH);
    // 10: cross = weights @ values -> bf16 + fp8(x16) into gatein[:, H:2H]
    gemm_nt_fp8<3><<<dim3(HH / 128, BB / 128), 256, GEMM_DYN_SMEM>>>(
        wts8, valsT8, cross, BB, HH, BB, 1.f / 1048576.f, 16.f, nullptr, nullptr, nullptr, gin8);
    // 11: Wg1 -> fp8 (x256)
    {
        long n4 = (long)GHH * 2 * HH / 4;
        f32_to_fp8_kernel<<<(unsigned)((n4 + 255) / 256), 256>>>(Wg1, wg18, 256.f, n4);
    }
    // 12: h1 = gelu(gatein @ Wg1^T + b1) -> fp8 (x64)   (desc 1/(16*256))
    gemm_nt_fp8<4><<<dim3(GHH / 128, BB / 128), 256, GEMM_DYN_SMEM>>>(
        gin8, wg18, h18, BB, GHH, 2 * HH, 1.f / 4096.f, 64.f, bg1, nullptr, nullptr, nullptr);
    // 13: Wg2 -> fp8 (x256)
    {
        long n4 = (long)HH * GHH / 4;
        f32_to_fp8_kernel<<<(unsigned)((n4 + 255) / 256), 256>>>(Wg2, wg28, 256.f, n4);
    }
    // 14: out = hidden + sigmoid(h1 @ Wg2^T + b2) * cross   (desc 1/(64*256))
    gemm_nt_fp8<5><<<dim3(HH / 128, BB / 128), 256, GEMM_DYN_SMEM>>>(
        h18, wg28, out, BB, HH, GHH, 1.f / 16384.f, 0.f, bg2, hidden, cross, nullptr);
}

// round 8
// speedup vs baseline: 1.4422x; 1.0701x over previous
#include <cuda_runtime.h>
#include <cuda_bf16.h>
#include <cuda_fp8.h>
#include <cstdint>
#include <math.h>

#define BB 8192
#define HH 4096
#define GHH 1024

// ---------------- scratch (device globals; allocation-free rule) ----------------
__device__ uint8_t       g_hidden8[(size_t)BB * HH];
__device__ uint8_t       g_Wsim8[(size_t)HH * HH];
__device__ uint8_t       g_Wval8[(size_t)HH * HH];
__device__ uint8_t       g_Wg18[(size_t)GHH * 2 * HH];
__device__ uint8_t       g_Wg28[(size_t)HH * GHH];
__device__ __nv_bfloat16 g_proj_bf[(size_t)BB * HH];
__device__ uint8_t       g_normed8[(size_t)BB * HH];
__device__ uint8_t       g_values8[(size_t)BB * HH];
__device__ uint8_t       g_valuesT8[(size_t)HH * BB];
__device__ float         g_sim_f32[(size_t)BB * BB];
__device__ uint8_t       g_weights8[(size_t)BB * BB];
__device__ __nv_bfloat16 g_cross_bf[(size_t)BB * HH];
__device__ uint8_t       g_gatein8[(size_t)BB * 2 * HH];
__device__ uint8_t       g_h18[(size_t)BB * GHH];
__device__ unsigned char g_mask_u8[BB];

// scales: hidden x16, W x256, normed x64, weights x65536, values x16, cross(gatein) x16, h1 x64

// ---------------- helpers ----------------
__device__ __forceinline__ uint32_t smem_u32(const void* p) {
    return (uint32_t)__cvta_generic_to_shared(p);
}
__device__ __forceinline__ uint8_t f2e4m3(float v) {
    return (uint8_t)__nv_cvt_float_to_fp8(v, __NV_SATFINITE, __NV_E4M3);
}

// ---------------- fused mask detect + expand (single block) ----------------
__global__ void mask_fused_kernel(const unsigned char* m, unsigned char* out) {
    __shared__ int s_nonbin, s_off4, s_fbad, s_bfbad, s_code;
    if (threadIdx.x == 0) { s_nonbin = 0; s_off4 = 0; s_fbad = 0; s_bfbad = 0; }
    __syncthreads();
    int nonbin = 0, off4 = 0, fbad = 0, bfbad = 0;
    for (int j = threadIdx.x; j < 8192; j += 256) {
        unsigned char b = m[j];
        if (b > 1) nonbin++;
        if ((j & 3) != 0 && b != 0) off4++;
    }
    const uint32_t* u = (const uint32_t*)m;
    for (int i = threadIdx.x; i < 2048; i += 256) {
        uint32_t w = u[i];
        if (!(w == 0u || w == 0x3f800000u)) fbad++;
    }
    const uint16_t* h = (const uint16_t*)m;
    for (int i = threadIdx.x; i < 4096; i += 256) {
        uint16_t x = h[i];
        if (!(x == 0 || x == 0x3f80)) bfbad++;
    }
    atomicAdd(&s_nonbin, nonbin);
    atomicAdd(&s_off4, off4);
    atomicAdd(&s_fbad, fbad);
    atomicAdd(&s_bfbad, bfbad);
    __syncthreads();
    if (threadIdx.x == 0) {
        int code;
        if (s_nonbin == 0) code = (s_off4 > 0) ? 0 : 1;
        else if (s_fbad == 0) code = 2;
        else if (s_bfbad == 0) code = 3;
        else code = 1;
        s_code = code;
    }
    __syncthreads();
    int code = s_code;
    for (int i = threadIdx.x; i < BB; i += 256) {
        bool v;
        if (code == 0)      v = ((const unsigned char*)m)[i] != 0;
        else if (code == 1) v = ((const int*)m)[i] != 0;
        else if (code == 2) v = ((const float*)m)[i] != 0.0f;
        else                v = (((const uint16_t*)m)[i] & 0x7fff) != 0;
        out[i] = v ? 1 : 0;
    }
}

// ---------------- fp32 -> fp8 convert (scale) ----------------
__global__ void f32_to_fp8_kernel(const float* __restrict__ in,
                                  uint8_t* __restrict__ out, float scale, long n4) {
    long i = (long)blockIdx.x * blockDim.x + threadIdx.x;
    if (i < n4) {
        float4 v = ((const float4*)in)[i];
        uint32_t p = (uint32_t)f2e4m3(v.x * scale) |
                     ((uint32_t)f2e4m3(v.y * scale) << 8) |
                     ((uint32_t)f2e4m3(v.z * scale) << 16) |
                     ((uint32_t)f2e4m3(v.w * scale) << 24);
        ((uint32_t*)out)[i] = p;
    }
}

// hidden -> g_hidden8 AND first half of g_gatein8, scale 16
__global__ void hidden_to_fp8_kernel(const float* __restrict__ in,
                                     uint8_t* __restrict__ out,
                                     uint8_t* __restrict__ gatein) {
    long i = ((long)blockIdx.x * blockDim.x + threadIdx.x);
    if (i >= (long)BB * HH / 4) return;
    float4 v = ((const float4*)in)[i];
    uint32_t p = (uint32_t)f2e4m3(v.x * 16.f) |
                 ((uint32_t)f2e4m3(v.y * 16.f) << 8) |
                 ((uint32_t)f2e4m3(v.z * 16.f) << 16) |
                 ((uint32_t)f2e4m3(v.w * 16.f) << 24);
    ((uint32_t*)out)[i] = p;
    long e = i * 4;
    long b = e >> 12;            // /HH
    int  j = (int)(e & (HH - 1));
    *(uint32_t*)(gatein + b * (2 * HH) + j) = p;
}

// ---------------- row L2 normalize: bf16 proj -> fp8 normed (x64) ----------------
__global__ void normalize_rows_kernel(const __nv_bfloat16* __restrict__ p,
                                      uint8_t* __restrict__ normed) {
    int row = blockIdx.x;
    const __nv_bfloat16* r = p + (size_t)row * HH;
    float s = 0.f;
    for (int j = threadIdx.x; j < HH; j += 256) {
        float v = __bfloat162float(r[j]);
        s += v * v;
    }
#pragma unroll
    for (int o = 16; o > 0; o >>= 1) s += __shfl_xor_sync(0xffffffffu, s, o);
    __shared__ float ws[8];
    int w = threadIdx.x >> 5, l = threadIdx.x & 31;
    if (l == 0) ws[w] = s;
    __syncthreads();
    if (threadIdx.x < 32) {
        float x = (threadIdx.x < 8) ? ws[threadIdx.x] : 0.f;
#pragma unroll
        for (int o = 4; o > 0; o >>= 1) x += __shfl_xor_sync(0xffffffffu, x, o);
        if (threadIdx.x == 0) ws[0] = x;
    }
    __syncthreads();
    float scale = 64.f / fmaxf(sqrtf(ws[0]), 1e-12f);
    uint8_t* nr = normed + (size_t)row * HH;
    for (int j = threadIdx.x; j < HH / 4; j += 256) {
        float v0 = __bfloat162float(r[j * 4 + 0]) * scale;
        float v1 = __bfloat162float(r[j * 4 + 1]) * scale;
        float v2 = __bfloat162float(r[j * 4 + 2]) * scale;
        float v3 = __bfloat162float(r[j * 4 + 3]) * scale;
        ((uint32_t*)nr)[j] = (uint32_t)f2e4m3(v0) | ((uint32_t)f2e4m3(v1) << 8) |
                             ((uint32_t)f2e4m3(v2) << 16) | ((uint32_t)f2e4m3(v3) << 24);
    }
}

// ---------------- masked softmax: f32 sim -> fp8 weights (x65536) ----------------
__global__ void softmax_mask_kernel(const float* __restrict__ sim,
                                    const unsigned char* __restrict__ mask,
                                    uint8_t* __restrict__ wts) {
    int row = blockIdx.x;
    __shared__ float sv[BB];
    __shared__ float red[8];
    const float* sr = sim + (size_t)row * BB;
    float mx = -INFINITY;
    for (int j = threadIdx.x; j < BB; j += 256) {
        float v = sr[j];
        if (j == row || mask[j] == 0) v = -INFINITY;
        sv[j] = v;
        mx = fmaxf(mx, v);
    }
#pragma unroll
    for (int o = 16; o > 0; o >>= 1) mx = fmaxf(mx, __shfl_xor_sync(0xffffffffu, mx, o));
    int w = threadIdx.x >> 5, l = threadIdx.x & 31;
    if (l == 0) red[w] = mx;
    __syncthreads();
    if (threadIdx.x < 32) {
        float x = (threadIdx.x < 8) ? red[threadIdx.x] : -INFINITY;
#pragma unroll
        for (int o = 4; o > 0; o >>= 1) x = fmaxf(x, __shfl_xor_sync(0xffffffffu, x, o));
        if (threadIdx.x == 0) red[0] = x;
    }
    __syncthreads();
    float M = red[0];
    __syncthreads();
    float sum = 0.f;
    for (int j = threadIdx.x; j < BB; j += 256) {
        float v = sv[j];
        float e = (v == -INFINITY) ? 0.f : __expf(v - M);
        sv[j] = e;
        sum += e;
    }
#pragma unroll
    for (int o = 16; o > 0; o >>= 1) sum += __shfl_xor_sync(0xffffffffu, sum, o);
    if (l == 0) red[w] = sum;
    __syncthreads();
    if (threadIdx.x < 32) {
        float x = (threadIdx.x < 8) ? red[threadIdx.x] : 0.f;
#pragma unroll
        for (int o = 4; o > 0; o >>= 1) x += __shfl_xor_sync(0xffffffffu, x, o);
        if (threadIdx.x == 0) red[0] = x;
    }
    __syncthreads();
    float S = red[0];
    float inv = (S > 0.f) ? 65536.f / S : 0.f;
    uint8_t* wr = wts + (size_t)row * BB;
    for (int j = threadIdx.x; j < BB / 4; j += 256) {
        ((uint32_t*)wr)[j] = (uint32_t)f2e4m3(sv[j * 4 + 0] * inv) |
                             ((uint32_t)f2e4m3(sv[j * 4 + 1] * inv) << 8) |
                             ((uint32_t)f2e4m3(sv[j * 4 + 2] * inv) << 16) |
                             ((uint32_t)f2e4m3(sv[j * 4 + 3] * inv) << 24);
    }
}

// ---------------- u8 transpose (values -> valuesT) ----------------
__global__ void transpose_u8_kernel(const uint8_t* __restrict__ in,
                                    uint8_t* __restrict__ out, int R, int C) {
    __shared__ uint8_t tile[32][33];
    int x = blockIdx.x * 32 + threadIdx.x;
    int y0 = blockIdx.y * 32 + threadIdx.y;
#pragma unroll
    for (int i = 0; i < 32; i += 8)
        tile[threadIdx.y + i][threadIdx.x] = in[(size_t)(y0 + i) * C + x];
    __syncthreads();
    int x2 = blockIdx.y * 32 + threadIdx.x;
    int y2 = blockIdx.x * 32 + threadIdx.y;
#pragma unroll
    for (int i = 0; i < 32; i += 8)
        out[(size_t)(y2 + i) * R + x2] = tile[threadIdx.x][threadIdx.y + i];
}

// ================= fp8 NT GEMM (mma.sync m16n8k32 e4m3): C = A * B^T =========
// CTA tile 128x64, warp tile 32x32 (8 warps 4Mx2N), K-stage 128 elements,
// 2-stage cp.async pipeline, 55.5KB smem + 85-reg cap -> 3 CTAs/SM (24 warps).
// Single __syncthreads per K-stage.
// EPI: 0=f32(desc), 1=bf16(desc), 2=fp8(desc*oscale),
//      3=cross: bf16 + fp8 into gatein second half,
//      4=gelu(desc*acc+bias)->fp8, 5=hid+sigmoid(desc*acc+bias)*cross->f32,
//      6=f32(desc) symmetric (M==N): skip tiles fully above diagonal, mirror-write
#define SROWB 144
#define A_BYTES (128 * SROWB)                 // 18432
#define B_BYTES (64 * SROWB)                  // 9216
#define STAGE_BYTES (A_BYTES + B_BYTES)       // 27648
#define GEMM_DYN_SMEM (2 * STAGE_BYTES + 256) // 55552

template <int EPI>
__global__ void __launch_bounds__(256, 3)
gemm_nt_fp8(const uint8_t* __restrict__ A,
            const uint8_t* __restrict__ Bm,
            void* __restrict__ Cv,
            int M, int N, int K,
            float desc, float oscale,
            const float* __restrict__ bias,
            const float* __restrict__ hid,
            const __nv_bfloat16* __restrict__ crossp,
            uint8_t* __restrict__ out2) {
    // symmetric: tile rows [m0,m0+128), cols [n0,n0+64); skip if fully above diagonal
    if (EPI == 6 && (int)blockIdx.x * 64 >= (int)blockIdx.y * 128 + 128) return;

    extern __shared__ char dynsm[];
    const uint32_t sbase = (smem_u32(dynsm) + 127u) & ~127u;

    const int t = threadIdx.x;
    const int warp = t >> 5, lane = t & 31;
    const int wm = (warp & 3) * 32;        // 4 warps over M
    const int wn = (warp >> 2) * 32;       // 2 warps over N
    const int m0 = blockIdx.y * 128;
    const int n0 = blockIdx.x * 64;
    const int KT = K >> 7;                 // 128-element K stages

    // ---- producer addressing ----
    const int frow = t >> 3;               // 0..31
    const int fchb = (t & 7) * 16;
    const uint32_t sAoff = (uint32_t)frow * SROWB + fchb;
    const uint32_t sBoff = A_BYTES + (uint32_t)frow * SROWB + fchb;
    const uint8_t* gA = A + (size_t)(m0 + frow) * K + fchb;
    const uint8_t* gB = Bm + (size_t)(n0 + frow) * K + fchb;   // frow<64 used for B

    // ---- consumer addressing ----
    const uint32_t aOff0 = (uint32_t)(wm + (lane & 15)) * SROWB + (lane >> 4) * 16;
    const uint32_t bOff0 = A_BYTES + (uint32_t)(wn + (lane & 15)) * SROWB + (lane >> 4) * 16;

    float acc[2][4][4];
#pragma unroll
    for (int i = 0; i < 2; i++)
#pragma unroll
        for (int j = 0; j < 4; j++)
#pragma unroll
            for (int r = 0; r < 4; r++) acc[i][j][r] = 0.f;

    auto fill = [&](int kt, int st) {
        const uint32_t stb = sbase + st * STAGE_BYTES;
        const size_t kb = (size_t)kt * 128;
#pragma unroll
        for (int i = 0; i < 4; i++) {          // A: 128 rows
            uint32_t dst = stb + sAoff + i * (32 * SROWB);
            const void* gp = gA + kb + (size_t)i * 32 * K;
            asm volatile("cp.async.cg.shared.global [%0], [%1], 16;\n" ::"r"(dst), "l"(gp));
        }
#pragma unroll
        for (int i = 0; i < 2; i++) {          // B: 64 rows
            uint32_t dst = stb + sBoff + i * (32 * SROWB);
            const void* gp = gB + kb + (size_t)i * 32 * K;
            asm volatile("cp.async.cg.shared.global [%0], [%1], 16;\n" ::"r"(dst), "l"(gp));
        }
    };

    fill(0, 0);
    asm volatile("cp.async.commit_group;\n" ::);

    for (int kt = 0; kt < KT; ++kt) {
        asm volatile("cp.async.wait_group 0;\n" ::);   // fill(kt) complete
        __syncthreads();                               // visible to all; compute(kt-1) done
        if (kt + 1 < KT) {
            fill(kt + 1, (kt + 1) & 1);                // overlaps compute(kt)
            asm volatile("cp.async.commit_group;\n" ::);
        }

        const uint32_t stb = sbase + (kt & 1) * STAGE_BYTES;
        const uint32_t aBase = stb + aOff0;
        const uint32_t bBase = stb + bOff0;
#pragma unroll
        for (int ks = 0; ks < 4; ++ks) {
            uint32_t af[2][4], bf[2][4];
#pragma unroll
            for (int i = 0; i < 2; i++) {
                uint32_t addr = aBase + (uint32_t)(i * 16 * SROWB + ks * 32);
                asm volatile("ldmatrix.sync.aligned.m8n8.x4.shared.b16 {%0,%1,%2,%3}, [%4];\n"
                             : "=r"(af[i][0]), "=r"(af[i][1]), "=r"(af[i][2]), "=r"(af[i][3])
                             : "r"(addr));
            }
#pragma unroll
            for (int jj = 0; jj < 2; jj++) {
                uint32_t addr = bBase + (uint32_t)(jj * 16 * SROWB + ks * 32);
                asm volatile("ldmatrix.sync.aligned.m8n8.x4.shared.b16 {%0,%1,%2,%3}, [%4];\n"
                             : "=r"(bf[jj][0]), "=r"(bf[jj][1]), "=r"(bf[jj][2]), "=r"(bf[jj][3])
                             : "r"(addr));
            }
#pragma unroll
            for (int i = 0; i < 2; i++) {
#pragma unroll
                for (int j = 0; j < 4; j++) {
                    const int jj = j >> 1, s = j & 1;
                    asm volatile(
                        "mma.sync.aligned.m16n8k32.row.col.f32.e4m3.e4m3.f32 "
                        "{%0,%1,%2,%3}, {%4,%5,%6,%7}, {%8,%9}, {%0,%1,%2,%3};\n"
                        : "+f"(acc[i][j][0]), "+f"(acc[i][j][1]),
                          "+f"(acc[i][j][2]), "+f"(acc[i][j][3])
                        : "r"(af[i][0]), "r"(af[i][1]), "r"(af[i][2]), "r"(af[i][3]),
                          "r"(bf[jj][s]), "r"(bf[jj][s + 2]));
                }
            }
        }
        __syncthreads();   // stage kt fully consumed before next iter's fill overwrites peer stage
    }

    // ----- epilogue -----
#pragma unroll
    for (int i = 0; i < 2; i++) {
        int row0 = m0 + wm + i * 16 + (lane >> 2);
#pragma unroll
        for (int j = 0; j < 4; j++) {
            int col = n0 + wn + j * 8 + (lane & 3) * 2;
#pragma unroll
            for (int h = 0; h < 2; h++) {
                int r = row0 + h * 8;
                float v0 = acc[i][j][h * 2 + 0] * desc;
                float v1 = acc[i][j][h * 2 + 1] * desc;
                size_t off = (size_t)r * N + col;
                if (EPI == 0) {
                    *(float2*)((float*)Cv + off) = make_float2(v0, v1);
                } else if (EPI == 6) {
                    *(float2*)((float*)Cv + off) = make_float2(v0, v1);
                    ((float*)Cv)[(size_t)col * N + r] = v0;
                    ((float*)Cv)[(size_t)(col + 1) * N + r] = v1;
                } else if (EPI == 1) {
                    *(__nv_bfloat162*)((__nv_bfloat16*)Cv + off) =
                        __floats2bfloat162_rn(v0, v1);
                } else if (EPI == 2) {
                    uint16_t p = (uint16_t)f2e4m3(v0 * oscale) |
                                 ((uint16_t)f2e4m3(v1 * oscale) << 8);
                    *(uint16_t*)((uint8_t*)Cv + off) = p;
                } else if (EPI == 3) {
                    *(__nv_bfloat162*)((__nv_bfloat16*)Cv + off) =
                        __floats2bfloat162_rn(v0, v1);
                    uint16_t p = (uint16_t)f2e4m3(v0 * oscale) |
                                 ((uint16_t)f2e4m3(v1 * oscale) << 8);
                    *(uint16_t*)(out2 + (size_t)r * (2 * HH) + HH + col) = p;
                } else if (EPI == 4) {
                    float x0 = v0 + bias[col], x1 = v1 + bias[col + 1];
                    float g0 = 0.5f * x0 * (1.f + erff(x0 * 0.70710678118654752f));
                    float g1 = 0.5f * x1 * (1.f + erff(x1 * 0.70710678118654752f));
                    uint16_t p = (uint16_t)f2e4m3(g0 * oscale) |
                                 ((uint16_t)f2e4m3(g1 * oscale) << 8);
                    *(uint16_t*)((uint8_t*)Cv + off) = p;
                } else {
                    float x0 = v0 + bias[col], x1 = v1 + bias[col + 1];
                    float s0 = 1.f / (1.f + expf(-x0));
                    float s1 = 1.f / (1.f + expf(-x1));
                    __nv_bfloat162 cc = *(const __nv_bfloat162*)(crossp + off);
                    float2 hv = *(const float2*)(hid + off);
                    *(float2*)((float*)Cv + off) =
                        make_float2(hv.x + s0 * __bfloat162float(cc.x),
                                    hv.y + s1 * __bfloat162float(cc.y));
                }
            }
        }
    }
}

// ---------------- host launcher ----------------
extern "C" void kernel_launch(void* const* d_in, const int* in_sizes, int n_in,
                              void* d_out, int out_size) {
    (void)in_sizes; (void)n_in; (void)out_size;
    const float* hidden = (const float*)d_in[0];
    const void*  amask  = d_in[1];
    const float* Wsim   = (const float*)d_in[2];
    const float* Wval   = (const float*)d_in[3];
    const float* Wg1    = (const float*)d_in[4];
    const float* bg1    = (const float*)d_in[5];
    const float* Wg2    = (const float*)d_in[6];
    const float* bg2    = (const float*)d_in[7];
    float* out = (float*)d_out;

    uint8_t *h8, *wsim8, *wval8, *wg18, *wg28, *normed8, *vals8, *valsT8, *wts8, *gin8, *h18;
    __nv_bfloat16 *proj, *cross;
    float* sim;
    unsigned char* mask;
    cudaGetSymbolAddress((void**)&h8,      g_hidden8);
    cudaGetSymbolAddress((void**)&wsim8,   g_Wsim8);
    cudaGetSymbolAddress((void**)&wval8,   g_Wval8);
    cudaGetSymbolAddress((void**)&wg18,    g_Wg18);
    cudaGetSymbolAddress((void**)&wg28,    g_Wg28);
    cudaGetSymbolAddress((void**)&proj,    g_proj_bf);
    cudaGetSymbolAddress((void**)&normed8, g_normed8);
    cudaGetSymbolAddress((void**)&vals8,   g_values8);
    cudaGetSymbolAddress((void**)&valsT8,  g_valuesT8);
    cudaGetSymbolAddress((void**)&sim,     g_sim_f32);
    cudaGetSymbolAddress((void**)&wts8,    g_weights8);
    cudaGetSymbolAddress((void**)&cross,   g_cross_bf);
    cudaGetSymbolAddress((void**)&gin8,    g_gatein8);
    cudaGetSymbolAddress((void**)&h18,     g_h18);
    cudaGetSymbolAddress((void**)&mask,    g_mask_u8);

    cudaFuncSetAttribute(gemm_nt_fp8<0>, cudaFuncAttributeMaxDynamicSharedMemorySize, GEMM_DYN_SMEM);
    cudaFuncSetAttribute(gemm_nt_fp8<1>, cudaFuncAttributeMaxDynamicSharedMemorySize, GEMM_DYN_SMEM);
    cudaFuncSetAttribute(gemm_nt_fp8<2>, cudaFuncAttributeMaxDynamicSharedMemorySize, GEMM_DYN_SMEM);
    cudaFuncSetAttribute(gemm_nt_fp8<3>, cudaFuncAttributeMaxDynamicSharedMemorySize, GEMM_DYN_SMEM);
    cudaFuncSetAttribute(gemm_nt_fp8<4>, cudaFuncAttributeMaxDynamicSharedMemorySize, GEMM_DYN_SMEM);
    cudaFuncSetAttribute(gemm_nt_fp8<5>, cudaFuncAttributeMaxDynamicSharedMemorySize, GEMM_DYN_SMEM);
    cudaFuncSetAttribute(gemm_nt_fp8<6>, cudaFuncAttributeMaxDynamicSharedMemorySize, GEMM_DYN_SMEM);

    // Launch order: ncu -s 5 -c 1 captures index 5 == sim GEMM (symmetric).
    // 0: fused mask
    mask_fused_kernel<<<1, 256>>>((const unsigned char*)amask, mask);
    // 1: hidden -> fp8 (x16) + gatein first half
    hidden_to_fp8_kernel<<<(unsigned)(((long)BB * HH / 4 + 255) / 256), 256>>>(hidden, h8, gin8);
    // 2: Wsim -> fp8 (x256)
    {
        long n4 = (long)HH * HH / 4;
        f32_to_fp8_kernel<<<(unsigned)((n4 + 255) / 256), 256>>>(Wsim, wsim8, 256.f, n4);
    }
    // 3: proj = hidden @ Wsim^T -> bf16   (desc 1/(16*256))
    gemm_nt_fp8<1><<<dim3(HH / 64, BB / 128), 256, GEMM_DYN_SMEM>>>(
        h8, wsim8, proj, BB, HH, HH, 1.f / 4096.f, 0.f, nullptr, nullptr, nullptr, nullptr);
    // 4: normalize -> normed fp8 (x64)
    normalize_rows_kernel<<<BB, 256>>>(proj, normed8);
    // 5: sim = normed @ normed^T -> f32, symmetric (desc 1/(64*64))  [ncu target]
    gemm_nt_fp8<6><<<dim3(BB / 64, BB / 128), 256, GEMM_DYN_SMEM>>>(
        normed8, normed8, sim, BB, BB, HH, 1.f / 4096.f, 0.f, nullptr, nullptr, nullptr, nullptr);
    // 6: Wval -> fp8 (x256)
    {
        long n4 = (long)HH * HH / 4;
        f32_to_fp8_kernel<<<(unsigned)((n4 + 255) / 256), 256>>>(Wval, wval8, 256.f, n4);
    }
    // 7: softmax -> weights fp8 (x65536)
    softmax_mask_kernel<<<BB, 256>>>(sim, mask, wts8);
    // 8: values = hidden @ Wval^T -> fp8 (x16)
    gemm_nt_fp8<2><<<dim3(HH / 64, BB / 128), 256, GEMM_DYN_SMEM>>>(
        h8, wval8, vals8, BB, HH, HH, 1.f / 4096.f, 16.f, nullptr, nullptr, nullptr, nullptr);
    // 9: transpose values -> valuesT
    transpose_u8_kernel<<<dim3(HH / 32, BB / 32), dim3(32, 8)>>>(vals8, valsT8, BB, HH);
    // 10: cross = weights @ values -> bf16 + fp8(x16) into gatein[:, H:2H]
    gemm_nt_fp8<3><<<dim3(HH / 64, BB / 128), 256, GEMM_DYN_SMEM>>>(
        wts8, valsT8, cross, BB, HH, BB, 1.f / 1048576.f, 16.f, nullptr, nullptr, nullptr, gin8);
    // 11: Wg1 -> fp8 (x256)
    {
        long n4 = (long)GHH * 2 * HH / 4;
        f32_to_fp8_kernel<<<(unsigned)((n4 + 255) / 256), 256>>>(Wg1, wg18, 256.f, n4);
    }
    // 12: h1 = gelu(gatein @ Wg1^T + b1) -> fp8 (x64)   (desc 1/(16*256))
    gemm_nt_fp8<4><<<dim3(GHH / 64, BB / 128), 256, GEMM_DYN_SMEM>>>(
        gin8, wg18, h18, BB, GHH, 2 * HH, 1.f / 4096.f, 64.f, bg1, nullptr, nullptr, nullptr);
    // 13: Wg2 -> fp8 (x256)
    {
        long n4 = (long)HH * GHH / 4;
        f32_to_fp8_kernel<<<(unsigned)((n4 + 255) / 256), 256>>>(Wg2, wg28, 256.f, n4);
    }
    // 14: out = hidden + sigmoid(h1 @ Wg2^T + b2) * cross   (desc 1/(64*256))
    gemm_nt_fp8<5><<<dim3(HH / 64, BB / 128), 256, GEMM_DYN_SMEM>>>(
        h18, wg28, out, BB, HH, GHH, 1.f / 16384.f, 0.f, bg2, hidden, cross, nullptr);
}

// round 9
// speedup vs baseline: 1.4906x; 1.0336x over previous
#include <cuda_runtime.h>
#include <cuda_bf16.h>
#include <cuda_fp8.h>
#include <cstdint>
#include <math.h>

#define BB 8192
#define HH 4096
#define GHH 1024

// ---------------- scratch (device globals; allocation-free rule) ----------------
__device__ uint8_t       g_hidden8[(size_t)BB * HH];
__device__ uint8_t       g_Wsim8[(size_t)HH * HH];
__device__ uint8_t       g_Wval8[(size_t)HH * HH];
__device__ uint8_t       g_Wg18[(size_t)GHH * 2 * HH];
__device__ uint8_t       g_Wg28[(size_t)HH * GHH];
__device__ __nv_bfloat16 g_proj_bf[(size_t)BB * HH];
__device__ uint8_t       g_normed8[(size_t)BB * HH];
__device__ uint8_t       g_values8[(size_t)BB * HH];
__device__ uint8_t       g_valuesT8[(size_t)HH * BB];
__device__ float         g_sim_f32[(size_t)BB * BB];
__device__ uint8_t       g_weights8[(size_t)BB * BB];
__device__ __nv_bfloat16 g_cross_bf[(size_t)BB * HH];
__device__ uint8_t       g_gatein8[(size_t)BB * 2 * HH];
__device__ uint8_t       g_h18[(size_t)BB * GHH];
__device__ unsigned char g_mask_u8[BB];

// scales: hidden x16, W x256, normed x64, weights x65536, values x16, cross(gatein) x16, h1 x64

// ---------------- helpers ----------------
__device__ __forceinline__ uint32_t smem_u32(const void* p) {
    return (uint32_t)__cvta_generic_to_shared(p);
}
__device__ __forceinline__ uint8_t f2e4m3(float v) {
    return (uint8_t)__nv_cvt_float_to_fp8(v, __NV_SATFINITE, __NV_E4M3);
}

// ---------------- fused mask detect + expand (single block) ----------------
__global__ void mask_fused_kernel(const unsigned char* m, unsigned char* out) {
    __shared__ int s_nonbin, s_off4, s_fbad, s_bfbad, s_code;
    if (threadIdx.x == 0) { s_nonbin = 0; s_off4 = 0; s_fbad = 0; s_bfbad = 0; }
    __syncthreads();
    int nonbin = 0, off4 = 0, fbad = 0, bfbad = 0;
    for (int j = threadIdx.x; j < 8192; j += 256) {
        unsigned char b = m[j];
        if (b > 1) nonbin++;
        if ((j & 3) != 0 && b != 0) off4++;
    }
    const uint32_t* u = (const uint32_t*)m;
    for (int i = threadIdx.x; i < 2048; i += 256) {
        uint32_t w = u[i];
        if (!(w == 0u || w == 0x3f800000u)) fbad++;
    }
    const uint16_t* h = (const uint16_t*)m;
    for (int i = threadIdx.x; i < 4096; i += 256) {
        uint16_t x = h[i];
        if (!(x == 0 || x == 0x3f80)) bfbad++;
    }
    atomicAdd(&s_nonbin, nonbin);
    atomicAdd(&s_off4, off4);
    atomicAdd(&s_fbad, fbad);
    atomicAdd(&s_bfbad, bfbad);
    __syncthreads();
    if (threadIdx.x == 0) {
        int code;
        if (s_nonbin == 0) code = (s_off4 > 0) ? 0 : 1;
        else if (s_fbad == 0) code = 2;
        else if (s_bfbad == 0) code = 3;
        else code = 1;
        s_code = code;
    }
    __syncthreads();
    int code = s_code;
    for (int i = threadIdx.x; i < BB; i += 256) {
        bool v;
        if (code == 0)      v = ((const unsigned char*)m)[i] != 0;
        else if (code == 1) v = ((const int*)m)[i] != 0;
        else if (code == 2) v = ((const float*)m)[i] != 0.0f;
        else                v = (((const uint16_t*)m)[i] & 0x7fff) != 0;
        out[i] = v ? 1 : 0;
    }
}

// ---------------- fp32 -> fp8 convert (scale) ----------------
__global__ void f32_to_fp8_kernel(const float* __restrict__ in,
                                  uint8_t* __restrict__ out, float scale, long n4) {
    long i = (long)blockIdx.x * blockDim.x + threadIdx.x;
    if (i < n4) {
        float4 v = ((const float4*)in)[i];
        uint32_t p = (uint32_t)f2e4m3(v.x * scale) |
                     ((uint32_t)f2e4m3(v.y * scale) << 8) |
                     ((uint32_t)f2e4m3(v.z * scale) << 16) |
                     ((uint32_t)f2e4m3(v.w * scale) << 24);
        ((uint32_t*)out)[i] = p;
    }
}

// hidden -> g_hidden8 AND first half of g_gatein8, scale 16
__global__ void hidden_to_fp8_kernel(const float* __restrict__ in,
                                     uint8_t* __restrict__ out,
                                     uint8_t* __restrict__ gatein) {
    long i = ((long)blockIdx.x * blockDim.x + threadIdx.x);
    if (i >= (long)BB * HH / 4) return;
    float4 v = ((const float4*)in)[i];
    uint32_t p = (uint32_t)f2e4m3(v.x * 16.f) |
                 ((uint32_t)f2e4m3(v.y * 16.f) << 8) |
                 ((uint32_t)f2e4m3(v.z * 16.f) << 16) |
                 ((uint32_t)f2e4m3(v.w * 16.f) << 24);
    ((uint32_t*)out)[i] = p;
    long e = i * 4;
    long b = e >> 12;            // /HH
    int  j = (int)(e & (HH - 1));
    *(uint32_t*)(gatein + b * (2 * HH) + j) = p;
}

// ---------------- row L2 normalize: bf16 proj -> fp8 normed (x64) ----------------
__global__ void normalize_rows_kernel(const __nv_bfloat16* __restrict__ p,
                                      uint8_t* __restrict__ normed) {
    int row = blockIdx.x;
    const __nv_bfloat16* r = p + (size_t)row * HH;
    float s = 0.f;
    for (int j = threadIdx.x; j < HH; j += 256) {
        float v = __bfloat162float(r[j]);
        s += v * v;
    }
#pragma unroll
    for (int o = 16; o > 0; o >>= 1) s += __shfl_xor_sync(0xffffffffu, s, o);
    __shared__ float ws[8];
    int w = threadIdx.x >> 5, l = threadIdx.x & 31;
    if (l == 0) ws[w] = s;
    __syncthreads();
    if (threadIdx.x < 32) {
        float x = (threadIdx.x < 8) ? ws[threadIdx.x] : 0.f;
#pragma unroll
        for (int o = 4; o > 0; o >>= 1) x += __shfl_xor_sync(0xffffffffu, x, o);
        if (threadIdx.x == 0) ws[0] = x;
    }
    __syncthreads();
    float scale = 64.f / fmaxf(sqrtf(ws[0]), 1e-12f);
    uint8_t* nr = normed + (size_t)row * HH;
    for (int j = threadIdx.x; j < HH / 4; j += 256) {
        float v0 = __bfloat162float(r[j * 4 + 0]) * scale;
        float v1 = __bfloat162float(r[j * 4 + 1]) * scale;
        float v2 = __bfloat162float(r[j * 4 + 2]) * scale;
        float v3 = __bfloat162float(r[j * 4 + 3]) * scale;
        ((uint32_t*)nr)[j] = (uint32_t)f2e4m3(v0) | ((uint32_t)f2e4m3(v1) << 8) |
                             ((uint32_t)f2e4m3(v2) << 16) | ((uint32_t)f2e4m3(v3) << 24);
    }
}

// ---------------- masked softmax: f32 sim -> fp8 weights (x65536) ----------------
__global__ void softmax_mask_kernel(const float* __restrict__ sim,
                                    const unsigned char* __restrict__ mask,
                                    uint8_t* __restrict__ wts) {
    int row = blockIdx.x;
    __shared__ float sv[BB];
    __shared__ float red[8];
    const float* sr = sim + (size_t)row * BB;
    float mx = -INFINITY;
    for (int j = threadIdx.x; j < BB; j += 256) {
        float v = sr[j];
        if (j == row || mask[j] == 0) v = -INFINITY;
        sv[j] = v;
        mx = fmaxf(mx, v);
    }
#pragma unroll
    for (int o = 16; o > 0; o >>= 1) mx = fmaxf(mx, __shfl_xor_sync(0xffffffffu, mx, o));
    int w = threadIdx.x >> 5, l = threadIdx.x & 31;
    if (l == 0) red[w] = mx;
    __syncthreads();
    if (threadIdx.x < 32) {
        float x = (threadIdx.x < 8) ? red[threadIdx.x] : -INFINITY;
#pragma unroll
        for (int o = 4; o > 0; o >>= 1) x = fmaxf(x, __shfl_xor_sync(0xffffffffu, x, o));
        if (threadIdx.x == 0) red[0] = x;
    }
    __syncthreads();
    float M = red[0];
    __syncthreads();
    float sum = 0.f;
    for (int j = threadIdx.x; j < BB; j += 256) {
        float v = sv[j];
        float e = (v == -INFINITY) ? 0.f : __expf(v - M);
        sv[j] = e;
        sum += e;
    }
#pragma unroll
    for (int o = 16; o > 0; o >>= 1) sum += __shfl_xor_sync(0xffffffffu, sum, o);
    if (l == 0) red[w] = sum;
    __syncthreads();
    if (threadIdx.x < 32) {
        float x = (threadIdx.x < 8) ? red[threadIdx.x] : 0.f;
#pragma unroll
        for (int o = 4; o > 0; o >>= 1) x += __shfl_xor_sync(0xffffffffu, x, o);
        if (threadIdx.x == 0) red[0] = x;
    }
    __syncthreads();
    float S = red[0];
    float inv = (S > 0.f) ? 65536.f / S : 0.f;
    uint8_t* wr = wts + (size_t)row * BB;
    for (int j = threadIdx.x; j < BB / 4; j += 256) {
        ((uint32_t*)wr)[j] = (uint32_t)f2e4m3(sv[j * 4 + 0] * inv) |
                             ((uint32_t)f2e4m3(sv[j * 4 + 1] * inv) << 8) |
                             ((uint32_t)f2e4m3(sv[j * 4 + 2] * inv) << 16) |
                             ((uint32_t)f2e4m3(sv[j * 4 + 3] * inv) << 24);
    }
}

// ---------------- u8 transpose (values -> valuesT) ----------------
__global__ void transpose_u8_kernel(const uint8_t* __restrict__ in,
                                    uint8_t* __restrict__ out, int R, int C) {
    __shared__ uint8_t tile[32][33];
    int x = blockIdx.x * 32 + threadIdx.x;
    int y0 = blockIdx.y * 32 + threadIdx.y;
#pragma unroll
    for (int i = 0; i < 32; i += 8)
        tile[threadIdx.y + i][threadIdx.x] = in[(size_t)(y0 + i) * C + x];
    __syncthreads();
    int x2 = blockIdx.y * 32 + threadIdx.x;
    int y2 = blockIdx.x * 32 + threadIdx.y;
#pragma unroll
    for (int i = 0; i < 32; i += 8)
        out[(size_t)(y2 + i) * R + x2] = tile[threadIdx.x][threadIdx.y + i];
}

// ================= fp8 NT GEMM (mma.sync m16n8k32 e4m3): C = A * B^T =========
// CTA tile 128x64, warp tile 32x32 (8 warps 4Mx2N), K-stage 128 bytes/row,
// XOR-swizzled smem (128B rows, chunk c at c^(r&7)) -> conflict-free ldmatrix.
// 3-stage cp.async pipeline, 72KB smem + 85-reg cap -> 3 CTAs/SM (24 warps).
// One __syncthreads per K-stage; fills issued 2 stages ahead.
// EPI: 0=f32(desc), 1=bf16(desc), 2=fp8(desc*oscale),
//      3=cross: bf16 + fp8 into gatein second half,
//      4=gelu(desc*acc+bias)->fp8, 5=hid+sigmoid(desc*acc+bias)*cross->f32,
//      6=f32(desc) symmetric (M==N): skip tiles fully above diagonal, mirror-write
#define A_BYTES (128 * 128)                   // 16384
#define B_BYTES (64 * 128)                    // 8192
#define STAGE_BYTES (A_BYTES + B_BYTES)       // 24576
#define GEMM_DYN_SMEM (3 * STAGE_BYTES + 256) // 73984

template <int EPI>
__global__ void __launch_bounds__(256, 3)
gemm_nt_fp8(const uint8_t* __restrict__ A,
            const uint8_t* __restrict__ Bm,
            void* __restrict__ Cv,
            int M, int N, int K,
            float desc, float oscale,
            const float* __restrict__ bias,
            const float* __restrict__ hid,
            const __nv_bfloat16* __restrict__ crossp,
            uint8_t* __restrict__ out2) {
    // symmetric: tile rows [m0,m0+128), cols [n0,n0+64); skip if fully above diagonal
    if (EPI == 6 && (int)blockIdx.x * 64 >= (int)blockIdx.y * 128 + 128) return;

    extern __shared__ char dynsm[];
    const uint32_t sbase = (smem_u32(dynsm) + 127u) & ~127u;

    const int t = threadIdx.x;
    const int warp = t >> 5, lane = t & 31;
    const int wm = (warp & 3) * 32;        // 4 warps over M
    const int wn = (warp >> 2) * 32;       // 2 warps over N
    const int m0 = blockIdx.y * 128;
    const int n0 = blockIdx.x * 64;
    const int KT = K >> 7;                 // 128-byte K stages

    // ---- producer addressing (XOR swizzle on 16B chunks) ----
    const int frow = t >> 3;               // 0..31
    const int fch = t & 7;                 // chunk 0..7
    const uint32_t swch = (uint32_t)(fch ^ (frow & 7)) * 16;
    const uint32_t sAoff = (uint32_t)frow * 128 + swch;
    const uint32_t sBoff = A_BYTES + (uint32_t)frow * 128 + swch;
    const uint8_t* gA = A + (size_t)(m0 + frow) * K + fch * 16;
    const uint8_t* gB = Bm + (size_t)(n0 + frow) * K + fch * 16;

    // ---- consumer addressing ----
    const int crow = lane & 15;            // row within 16-row frag block
    const int hi = lane >> 4;              // chunk low bit
    const int rx = crow & 7;               // XOR key (same for A and B rows)
    const uint32_t aRow0 = (uint32_t)(wm + crow) * 128;          // + stage base
    const uint32_t bRow0 = A_BYTES + (uint32_t)(wn + crow) * 128;

    float acc[2][4][4];
#pragma unroll
    for (int i = 0; i < 2; i++)
#pragma unroll
        for (int j = 0; j < 4; j++)
#pragma unroll
            for (int r = 0; r < 4; r++) acc[i][j][r] = 0.f;

    auto fill = [&](int kt, int st) {
        const uint32_t stb = sbase + st * STAGE_BYTES;
        const size_t kb = (size_t)kt * 128;
#pragma unroll
        for (int i = 0; i < 4; i++) {          // A: 128 rows
            uint32_t dst = stb + sAoff + i * (32 * 128);
            const void* gp = gA + kb + (size_t)i * 32 * K;
            asm volatile("cp.async.cg.shared.global [%0], [%1], 16;\n" ::"r"(dst), "l"(gp));
        }
#pragma unroll
        for (int i = 0; i < 2; i++) {          // B: 64 rows
            uint32_t dst = stb + sBoff + i * (32 * 128);
            const void* gp = gB + kb + (size_t)i * 32 * K;
            asm volatile("cp.async.cg.shared.global [%0], [%1], 16;\n" ::"r"(dst), "l"(gp));
        }
    };

    fill(0, 0);
    asm volatile("cp.async.commit_group;\n" ::);
    if (KT > 1) { fill(1, 1); }
    asm volatile("cp.async.commit_group;\n" ::);

    int st = 0;                                // stage of kt
    for (int kt = 0; kt < KT; ++kt) {
        asm volatile("cp.async.wait_group 1;\n" ::);   // fill(kt) done (fill(kt+1) may fly)
        __syncthreads();                               // + compute(kt-1) finished by all
        if (kt + 2 < KT) {
            int s2 = st - 1; if (s2 < 0) s2 += 3;      // (kt+2)%3
            fill(kt + 2, s2);
        }
        asm volatile("cp.async.commit_group;\n" ::);   // (dummy in tail keeps count)

        const uint32_t stb = sbase + st * STAGE_BYTES;
        const uint32_t aBase = stb + aRow0;
        const uint32_t bBase = stb + bRow0;
#pragma unroll
        for (int ks = 0; ks < 4; ++ks) {
            const uint32_t swoff = (uint32_t)(((2 * ks + hi) ^ rx) << 4);
            uint32_t af[2][4], bf[2][4];
#pragma unroll
            for (int i = 0; i < 2; i++) {
                uint32_t addr = aBase + swoff + i * (16 * 128);
                asm volatile("ldmatrix.sync.aligned.m8n8.x4.shared.b16 {%0,%1,%2,%3}, [%4];\n"
                             : "=r"(af[i][0]), "=r"(af[i][1]), "=r"(af[i][2]), "=r"(af[i][3])
                             : "r"(addr));
            }
#pragma unroll
            for (int jj = 0; jj < 2; jj++) {
                uint32_t addr = bBase + swoff + jj * (16 * 128);
                asm volatile("ldmatrix.sync.aligned.m8n8.x4.shared.b16 {%0,%1,%2,%3}, [%4];\n"
                             : "=r"(bf[jj][0]), "=r"(bf[jj][1]), "=r"(bf[jj][2]), "=r"(bf[jj][3])
                             : "r"(addr));
            }
#pragma unroll
            for (int i = 0; i < 2; i++) {
#pragma unroll
                for (int j = 0; j < 4; j++) {
                    const int jj = j >> 1, s = j & 1;
                    asm volatile(
                        "mma.sync.aligned.m16n8k32.row.col.f32.e4m3.e4m3.f32 "
                        "{%0,%1,%2,%3}, {%4,%5,%6,%7}, {%8,%9}, {%0,%1,%2,%3};\n"
                        : "+f"(acc[i][j][0]), "+f"(acc[i][j][1]),
                          "+f"(acc[i][j][2]), "+f"(acc[i][j][3])
                        : "r"(af[i][0]), "r"(af[i][1]), "r"(af[i][2]), "r"(af[i][3]),
                          "r"(bf[jj][s]), "r"(bf[jj][s + 2]));
                }
            }
        }
        if (++st == 3) st = 0;
    }

    // ----- epilogue -----
#pragma unroll
    for (int i = 0; i < 2; i++) {
        int row0 = m0 + wm + i * 16 + (lane >> 2);
#pragma unroll
        for (int j = 0; j < 4; j++) {
            int col = n0 + wn + j * 8 + (lane & 3) * 2;
#pragma unroll
            for (int h = 0; h < 2; h++) {
                int r = row0 + h * 8;
                float v0 = acc[i][j][h * 2 + 0] * desc;
                float v1 = acc[i][j][h * 2 + 1] * desc;
                size_t off = (size_t)r * N + col;
                if (EPI == 0) {
                    *(float2*)((float*)Cv + off) = make_float2(v0, v1);
                } else if (EPI == 6) {
                    *(float2*)((float*)Cv + off) = make_float2(v0, v1);
                    ((float*)Cv)[(size_t)col * N + r] = v0;
                    ((float*)Cv)[(size_t)(col + 1) * N + r] = v1;
                } else if (EPI == 1) {
                    *(__nv_bfloat162*)((__nv_bfloat16*)Cv + off) =
                        __floats2bfloat162_rn(v0, v1);
                } else if (EPI == 2) {
                    uint16_t p = (uint16_t)f2e4m3(v0 * oscale) |
                                 ((uint16_t)f2e4m3(v1 * oscale) << 8);
                    *(uint16_t*)((uint8_t*)Cv + off) = p;
                } else if (EPI == 3) {
                    *(__nv_bfloat162*)((__nv_bfloat16*)Cv + off) =
                        __floats2bfloat162_rn(v0, v1);
                    uint16_t p = (uint16_t)f2e4m3(v0 * oscale) |
                                 ((uint16_t)f2e4m3(v1 * oscale) << 8);
                    *(uint16_t*)(out2 + (size_t)r * (2 * HH) + HH + col) = p;
                } else if (EPI == 4) {
                    float x0 = v0 + bias[col], x1 = v1 + bias[col + 1];
                    float g0 = 0.5f * x0 * (1.f + erff(x0 * 0.70710678118654752f));
                    float g1 = 0.5f * x1 * (1.f + erff(x1 * 0.70710678118654752f));
                    uint16_t p = (uint16_t)f2e4m3(g0 * oscale) |
                                 ((uint16_t)f2e4m3(g1 * oscale) << 8);
                    *(uint16_t*)((uint8_t*)Cv + off) = p;
                } else {
                    float x0 = v0 + bias[col], x1 = v1 + bias[col + 1];
                    float s0 = 1.f / (1.f + expf(-x0));
                    float s1 = 1.f / (1.f + expf(-x1));
                    __nv_bfloat162 cc = *(const __nv_bfloat162*)(crossp + off);
                    float2 hv = *(const float2*)(hid + off);
                    *(float2*)((float*)Cv + off) =
                        make_float2(hv.x + s0 * __bfloat162float(cc.x),
                                    hv.y + s1 * __bfloat162float(cc.y));
                }
            }
        }
    }
}

// ---------------- host launcher ----------------
extern "C" void kernel_launch(void* const* d_in, const int* in_sizes, int n_in,
                              void* d_out, int out_size) {
    (void)in_sizes; (void)n_in; (void)out_size;
    const float* hidden = (const float*)d_in[0];
    const void*  amask  = d_in[1];
    const float* Wsim   = (const float*)d_in[2];
    const float* Wval   = (const float*)d_in[3];
    const float* Wg1    = (const float*)d_in[4];
    const float* bg1    = (const float*)d_in[5];
    const float* Wg2    = (const float*)d_in[6];
    const float* bg2    = (const float*)d_in[7];
    float* out = (float*)d_out;

    uint8_t *h8, *wsim8, *wval8, *wg18, *wg28, *normed8, *vals8, *valsT8, *wts8, *gin8, *h18;
    __nv_bfloat16 *proj, *cross;
    float* sim;
    unsigned char* mask;
    cudaGetSymbolAddress((void**)&h8,      g_hidden8);
    cudaGetSymbolAddress((void**)&wsim8,   g_Wsim8);
    cudaGetSymbolAddress((void**)&wval8,   g_Wval8);
    cudaGetSymbolAddress((void**)&wg18,    g_Wg18);
    cudaGetSymbolAddress((void**)&wg28,    g_Wg28);
    cudaGetSymbolAddress((void**)&proj,    g_proj_bf);
    cudaGetSymbolAddress((void**)&normed8, g_normed8);
    cudaGetSymbolAddress((void**)&vals8,   g_values8);
    cudaGetSymbolAddress((void**)&valsT8,  g_valuesT8);
    cudaGetSymbolAddress((void**)&sim,     g_sim_f32);
    cudaGetSymbolAddress((void**)&wts8,    g_weights8);
    cudaGetSymbolAddress((void**)&cross,   g_cross_bf);
    cudaGetSymbolAddress((void**)&gin8,    g_gatein8);
    cudaGetSymbolAddress((void**)&h18,     g_h18);
    cudaGetSymbolAddress((void**)&mask,    g_mask_u8);

    cudaFuncSetAttribute(gemm_nt_fp8<0>, cudaFuncAttributeMaxDynamicSharedMemorySize, GEMM_DYN_SMEM);
    cudaFuncSetAttribute(gemm_nt_fp8<1>, cudaFuncAttributeMaxDynamicSharedMemorySize, GEMM_DYN_SMEM);
    cudaFuncSetAttribute(gemm_nt_fp8<2>, cudaFuncAttributeMaxDynamicSharedMemorySize, GEMM_DYN_SMEM);
    cudaFuncSetAttribute(gemm_nt_fp8<3>, cudaFuncAttributeMaxDynamicSharedMemorySize, GEMM_DYN_SMEM);
    cudaFuncSetAttribute(gemm_nt_fp8<4>, cudaFuncAttributeMaxDynamicSharedMemorySize, GEMM_DYN_SMEM);
    cudaFuncSetAttribute(gemm_nt_fp8<5>, cudaFuncAttributeMaxDynamicSharedMemorySize, GEMM_DYN_SMEM);
    cudaFuncSetAttribute(gemm_nt_fp8<6>, cudaFuncAttributeMaxDynamicSharedMemorySize, GEMM_DYN_SMEM);

    // Launch order: ncu -s 5 -c 1 captures index 5 == sim GEMM (symmetric).
    // 0: fused mask
    mask_fused_kernel<<<1, 256>>>((const unsigned char*)amask, mask);
    // 1: hidden -> fp8 (x16) + gatein first half
    hidden_to_fp8_kernel<<<(unsigned)(((long)BB * HH / 4 + 255) / 256), 256>>>(hidden, h8, gin8);
    // 2: Wsim -> fp8 (x256)
    {
        long n4 = (long)HH * HH / 4;
        f32_to_fp8_kernel<<<(unsigned)((n4 + 255) / 256), 256>>>(Wsim, wsim8, 256.f, n4);
    }
    // 3: proj = hidden @ Wsim^T -> bf16   (desc 1/(16*256))
    gemm_nt_fp8<1><<<dim3(HH / 64, BB / 128), 256, GEMM_DYN_SMEM>>>(
        h8, wsim8, proj, BB, HH, HH, 1.f / 4096.f, 0.f, nullptr, nullptr, nullptr, nullptr);
    // 4: normalize -> normed fp8 (x64)
    normalize_rows_kernel<<<BB, 256>>>(proj, normed8);
    // 5: sim = normed @ normed^T -> f32, symmetric (desc 1/(64*64))  [ncu target]
    gemm_nt_fp8<6><<<dim3(BB / 64, BB / 128), 256, GEMM_DYN_SMEM>>>(
        normed8, normed8, sim, BB, BB, HH, 1.f / 4096.f, 0.f, nullptr, nullptr, nullptr, nullptr);
    // 6: Wval -> fp8 (x256)
    {
        long n4 = (long)HH * HH / 4;
        f32_to_fp8_kernel<<<(unsigned)((n4 + 255) / 256), 256>>>(Wval, wval8, 256.f, n4);
    }
    // 7: softmax -> weights fp8 (x65536)
    softmax_mask_kernel<<<BB, 256>>>(sim, mask, wts8);
    // 8: values = hidden @ Wval^T -> fp8 (x16)
    gemm_nt_fp8<2><<<dim3(HH / 64, BB / 128), 256, GEMM_DYN_SMEM>>>(
        h8, wval8, vals8, BB, HH, HH, 1.f / 4096.f, 16.f, nullptr, nullptr, nullptr, nullptr);
    // 9: transpose values -> valuesT
    transpose_u8_kernel<<<dim3(HH / 32, BB / 32), dim3(32, 8)>>>(vals8, valsT8, BB, HH);
    // 10: cross = weights @ values -> bf16 + fp8(x16) into gatein[:, H:2H]
    gemm_nt_fp8<3><<<dim3(HH / 64, BB / 128), 256, GEMM_DYN_SMEM>>>(
        wts8, valsT8, cross, BB, HH, BB, 1.f / 1048576.f, 16.f, nullptr, nullptr, nullptr, gin8);
    // 11: Wg1 -> fp8 (x256)
    {
        long n4 = (long)GHH * 2 * HH / 4;
        f32_to_fp8_kernel<<<(unsigned)((n4 + 255) / 256), 256>>>(Wg1, wg18, 256.f, n4);
    }
    // 12: h1 = gelu(gatein @ Wg1^T + b1) -> fp8 (x64)   (desc 1/(16*256))
    gemm_nt_fp8<4><<<dim3(GHH / 64, BB / 128), 256, GEMM_DYN_SMEM>>>(
        gin8, wg18, h18, BB, GHH, 2 * HH, 1.f / 4096.f, 64.f, bg1, nullptr, nullptr, nullptr);
    // 13: Wg2 -> fp8 (x256)
    {
        long n4 = (long)HH * GHH / 4;
        f32_to_fp8_kernel<<<(unsigned)((n4 + 255) / 256), 256>>>(Wg2, wg28, 256.f, n4);
    }
    // 14: out = hidden + sigmoid(h1 @ Wg2^T + b2) * cross   (desc 1/(64*256))
    gemm_nt_fp8<5><<<dim3(HH / 64, BB / 128), 256, GEMM_DYN_SMEM>>>(
        h18, wg28, out, BB, HH, GHH, 1.f / 16384.f, 0.f, bg2, hidden, cross, nullptr);
}